// round 11
// baseline (speedup 1.0000x reference)
#include <cuda_runtime.h>
#include <cuda_bf16.h>
#include <cstdint>

#define EMBED 1024
#define NHEAD 16
#define HDIM  64
#define BATCH 2
#define SEQ   2048
#define MROWS (BATCH*SEQ)   // 4096

// tf32-rounded copies of inputs / weights
__device__ float g_qc[MROWS*EMBED];
__device__ float g_kc[MROWS*EMBED];
__device__ float g_vc[MROWS*EMBED];
__device__ float g_w4[4*EMBED*EMBED];         // Wq | Wk | Wv | Wo
// bf16 hi/lo projections, [B,H,T,D]
__device__ __nv_bfloat16 g_qh[BATCH*NHEAD*SEQ*HDIM];
__device__ __nv_bfloat16 g_ql[BATCH*NHEAD*SEQ*HDIM];
__device__ __nv_bfloat16 g_kh[BATCH*NHEAD*SEQ*HDIM];
__device__ __nv_bfloat16 g_kl[BATCH*NHEAD*SEQ*HDIM];
__device__ __nv_bfloat16 g_vh[BATCH*NHEAD*SEQ*HDIM];
__device__ __nv_bfloat16 g_vl[BATCH*NHEAD*SEQ*HDIM];
__device__ float g_ao[MROWS*EMBED];           // attention out, [B,T,E] (tf32-rounded)

__device__ __forceinline__ uint32_t f2tf32(float x) {
    uint32_t r;
    asm("cvt.rna.tf32.f32 %0, %1;" : "=r"(r) : "f"(x));
    return r;
}

// ---------------------------------------------------------------------------
// Prepass: round inputs + weights to tf32 into device copies.
// ---------------------------------------------------------------------------
__global__ __launch_bounds__(256) void prepass(
    const float* __restrict__ q, const float* __restrict__ k, const float* __restrict__ v,
    const float* __restrict__ Wq, const float* __restrict__ Wk,
    const float* __restrict__ Wv, const float* __restrict__ Wo)
{
    int idx = blockIdx.x * 256 + threadIdx.x;       // float4 index
    const float* src; float* dst; int off;
    if (idx < 3145728) {
        int seg = idx >> 20;
        off = idx & 1048575;
        src = (seg == 0) ? q : (seg == 1) ? k : v;
        dst = (seg == 0) ? g_qc : (seg == 1) ? g_kc : g_vc;
    } else {
        int r = idx - 3145728;
        int seg = r >> 18;
        off = r & 262143;
        src = (seg == 0) ? Wq : (seg == 1) ? Wk : (seg == 2) ? Wv : Wo;
        dst = g_w4 + (size_t)seg * EMBED * EMBED;
    }
    float4 x = reinterpret_cast<const float4*>(src)[off];
    uint4 t = make_uint4(f2tf32(x.x), f2tf32(x.y), f2tf32(x.z), f2tf32(x.w));
    reinterpret_cast<uint4*>(dst)[off] = t;
}

// ---------------------------------------------------------------------------
// TF32 tensor-core GEMM: C = A @ W^T + bias. Inputs pre-rounded to tf32.
// 3-stage cp.async pipeline, ONE __syncthreads per chunk, wait_group 1.
// BK=32, pitch 36 words (conflict-free frags). Smem 110.6 KB -> 2 CTAs/SM.
// ---------------------------------------------------------------------------
__device__ __forceinline__ void mma_tf32(float* c, const uint32_t* a,
                                         uint32_t b0, uint32_t b1) {
    asm volatile(
        "mma.sync.aligned.m16n8k8.row.col.f32.tf32.tf32.f32 "
        "{%0,%1,%2,%3}, {%4,%5,%6,%7}, {%8,%9}, {%0,%1,%2,%3};"
        : "+f"(c[0]), "+f"(c[1]), "+f"(c[2]), "+f"(c[3])
        : "r"(a[0]), "r"(a[1]), "r"(a[2]), "r"(a[3]), "r"(b0), "r"(b1));
}

__device__ __forceinline__ uint32_t smem_u32(const void* p) {
    uint32_t a;
    asm("{ .reg .u64 t; cvta.to.shared.u64 t, %1; cvt.u32.u64 %0, t; }" : "=r"(a) : "l"(p));
    return a;
}

#define GP 36                    // words per row (32 + 4 pad)
#define GA_WORDS (128*GP)        // 4608 words
#define GSTAGE   (2*GA_WORDS)    // A + W per stage = 9216 words
#define GSTAGES  3
#define GEMM_SMEM (GSTAGES*GSTAGE*4)   // 110592 bytes

template<bool BHTD>
__device__ __forceinline__ void gemm_body(
    const float* __restrict__ A, const float* __restrict__ W,
    const float* __restrict__ bias, float* __restrict__ Cf,
    __nv_bfloat16* __restrict__ Ch, __nv_bfloat16* __restrict__ Cl,
    int m0, int n0)
{
    const int K = EMBED;
    extern __shared__ uint32_t gsm[];
    uint32_t sbase = smem_u32(gsm);

    int tid  = threadIdx.x;
    int lane = tid & 31;
    int warp = tid >> 5;
    int wm = warp >> 1, wn = warp & 1;
    int m0w = wm * 32, n0w = wn * 64;

    float c[2][8][4];
    #pragma unroll
    for (int mi = 0; mi < 2; mi++)
        #pragma unroll
        for (int ni = 0; ni < 8; ni++)
            #pragma unroll
            for (int q = 0; q < 4; q++) c[mi][ni][q] = 0.f;

    auto issue = [&](int ch, int s) {
        int k0 = ch * 32;
        #pragma unroll
        for (int i = 0; i < 4; i++) {
            int idx = tid + i*256;
            int r = idx >> 3, c4 = (idx & 7) << 2;
            uint32_t da = sbase + (uint32_t)(s*GSTAGE + r*GP + c4) * 4u;
            const float* ga = A + (size_t)(m0 + r) * K + k0 + c4;
            asm volatile("cp.async.cg.shared.global [%0], [%1], 16;" :: "r"(da), "l"(ga));
            uint32_t dw = da + GA_WORDS * 4u;
            const float* gw = W + (size_t)(n0 + r) * K + k0 + c4;
            asm volatile("cp.async.cg.shared.global [%0], [%1], 16;" :: "r"(dw), "l"(gw));
        }
        asm volatile("cp.async.commit_group;" ::: "memory");
    };

    const int NCHUNK = K / 32;   // 32
    issue(0, 0);
    issue(1, 1);

    for (int ch = 0; ch < NCHUNK; ch++) {
        asm volatile("cp.async.wait_group 1;" ::: "memory");   // group ch landed
        __syncthreads();                                       // all warps past compute(ch-1)
        if (ch + 2 < NCHUNK) issue(ch + 2, (ch + 2) % GSTAGES);

        const uint32_t* As = gsm + (ch % GSTAGES) * GSTAGE;
        const uint32_t* Ws = As + GA_WORDS;
        #pragma unroll
        for (int kk = 0; kk < 32; kk += 8) {
            int kb = kk + (lane & 3);
            uint32_t a[2][4];
            #pragma unroll
            for (int mi = 0; mi < 2; mi++) {
                int r = m0w + mi * 16 + (lane >> 2);
                a[mi][0] = As[r*GP + kb];
                a[mi][1] = As[(r + 8)*GP + kb];
                a[mi][2] = As[r*GP + kb + 4];
                a[mi][3] = As[(r + 8)*GP + kb + 4];
            }
            #pragma unroll
            for (int ni = 0; ni < 8; ni++) {
                int rn = n0w + ni * 8 + (lane >> 2);
                uint32_t b0 = Ws[rn*GP + kb];
                uint32_t b1 = Ws[rn*GP + kb + 4];
                mma_tf32(c[0][ni], a[0], b0, b1);
                mma_tf32(c[1][ni], a[1], b0, b1);
            }
        }
    }

    #pragma unroll
    for (int mi = 0; mi < 2; mi++) {
        int rbase = m0 + m0w + mi * 16 + (lane >> 2);
        #pragma unroll
        for (int ni = 0; ni < 8; ni++) {
            int col = n0 + n0w + ni * 8 + 2 * (lane & 3);    // even
            float bv0 = bias[col], bv1 = bias[col + 1];
            #pragma unroll
            for (int half = 0; half < 2; half++) {
                int m = rbase + half * 8;
                float v0 = c[mi][ni][half * 2 + 0] + bv0;
                float v1 = c[mi][ni][half * 2 + 1] + bv1;
                if (BHTD) {
                    int b = m >> 11, t = m & 2047;
                    int h = col >> 6, d = col & 63;          // d even, d+1 same head
                    size_t base = (((size_t)(b * NHEAD + h)) * SEQ + t) * HDIM + d;
                    __nv_bfloat16 h0 = __float2bfloat16(v0), h1 = __float2bfloat16(v1);
                    __nv_bfloat162 hp; hp.x = h0; hp.y = h1;
                    __nv_bfloat162 lp;
                    lp.x = __float2bfloat16(v0 - __bfloat162float(h0));
                    lp.y = __float2bfloat16(v1 - __bfloat162float(h1));
                    reinterpret_cast<uint32_t*>(Ch)[base >> 1] = *reinterpret_cast<uint32_t*>(&hp);
                    reinterpret_cast<uint32_t*>(Cl)[base >> 1] = *reinterpret_cast<uint32_t*>(&lp);
                } else {
                    Cf[(size_t)m * EMBED + col]     = v0;
                    Cf[(size_t)m * EMBED + col + 1] = v1;
                }
            }
        }
    }
}

__global__ __launch_bounds__(256) void gemm_qkv(
    const float* __restrict__ bq, const float* __restrict__ bk, const float* __restrict__ bv)
{
    int z = blockIdx.z;
    const float* A = (z == 0) ? g_qc : (z == 1) ? g_kc : g_vc;
    const float* W = g_w4 + (size_t)z * EMBED * EMBED;
    const float* B = (z == 0) ? bq : (z == 1) ? bk : bv;
    __nv_bfloat16* Ch = (z == 0) ? g_qh : (z == 1) ? g_kh : g_vh;
    __nv_bfloat16* Cl = (z == 0) ? g_ql : (z == 1) ? g_kl : g_vl;
    gemm_body<true>(A, W, B, nullptr, Ch, Cl, blockIdx.y * 128, blockIdx.x * 128);
}

__global__ __launch_bounds__(256) void gemm_out(
    const float* __restrict__ bias, float* __restrict__ C)
{
    gemm_body<false>(g_ao, g_w4 + (size_t)3 * EMBED * EMBED, bias, C,
                     nullptr, nullptr, blockIdx.y * 128, blockIdx.x * 128);
}

// ---------------------------------------------------------------------------
// Flash attention via bf16 split mma (hi+lo), unchanged from R10.
// ---------------------------------------------------------------------------
__device__ __forceinline__ void mma_bf16(float* c, const uint32_t* a,
                                         uint32_t b0, uint32_t b1) {
    asm volatile(
        "mma.sync.aligned.m16n8k16.row.col.f32.bf16.bf16.f32 "
        "{%0,%1,%2,%3}, {%4,%5,%6,%7}, {%8,%9}, {%0,%1,%2,%3};"
        : "+f"(c[0]), "+f"(c[1]), "+f"(c[2]), "+f"(c[3])
        : "r"(a[0]), "r"(a[1]), "r"(a[2]), "r"(a[3]), "r"(b0), "r"(b1));
}

__device__ __forceinline__ void pack2(float x, float y, uint32_t& hi, uint32_t& lo) {
    __nv_bfloat16 hx = __float2bfloat16(x), hy = __float2bfloat16(y);
    __nv_bfloat162 h2; h2.x = hx; h2.y = hy;
    hi = *reinterpret_cast<uint32_t*>(&h2);
    __nv_bfloat162 l2;
    l2.x = __float2bfloat16(x - __bfloat162float(hx));
    l2.y = __float2bfloat16(y - __bfloat162float(hy));
    lo = *reinterpret_cast<uint32_t*>(&l2);
}

#define FPITCH 72
#define FLASH_SMEM ((128*2 + 64*4) * FPITCH * 2 + 64 * 4)   // 73984

__global__ __launch_bounds__(256, 1) void flash_attn_mma(const unsigned char* __restrict__ mask)
{
    extern __shared__ __align__(16) char smraw[];
    __nv_bfloat16* sQh = (__nv_bfloat16*)smraw;
    __nv_bfloat16* sQl = sQh + 128*FPITCH;
    __nv_bfloat16* sKh = sQl + 128*FPITCH;
    __nv_bfloat16* sKl = sKh + 64*FPITCH;
    __nv_bfloat16* sVh = sKl + 64*FPITCH;     // transposed: [d][s]
    __nv_bfloat16* sVl = sVh + 64*FPITCH;
    float* mfs = (float*)(sVl + 64*FPITCH);   // 64 floats

    int tid  = threadIdx.x;
    int lane = tid & 31, warp = tid >> 5;
    int grp  = lane >> 2, thr4 = lane & 3;
    int qt = (int)gridDim.x - 1 - (int)blockIdx.x;   // heavy tiles first
    int h = blockIdx.y, b = blockIdx.z;
    int qbase = qt * 128;

    size_t headoff = ((size_t)(b*NHEAD + h))*SEQ*HDIM;
    const uint32_t* Qh32 = (const uint32_t*)g_qh + (headoff + (size_t)qbase*HDIM)/2;
    const uint32_t* Ql32 = (const uint32_t*)g_ql + (headoff + (size_t)qbase*HDIM)/2;
    const uint32_t* Kh32 = (const uint32_t*)g_kh + headoff/2;
    const uint32_t* Kl32 = (const uint32_t*)g_kl + headoff/2;
    const uint32_t* Vh32 = (const uint32_t*)g_vh + headoff/2;
    const uint32_t* Vl32 = (const uint32_t*)g_vl + headoff/2;
    const unsigned char* km = mask + (size_t)b*SEQ;

    // ---- stage Q (pure copy) ----
    #pragma unroll
    for (int i = 0; i < 8; i++) {
        int e = tid + i*256;
        int r = e >> 4, c4 = (e & 15) << 2;
        int gi = (r*HDIM + c4) >> 1;
        *reinterpret_cast<uint2*>(sQh + r*FPITCH + c4) = *reinterpret_cast<const uint2*>(Qh32 + gi);
        *reinterpret_cast<uint2*>(sQl + r*FPITCH + c4) = *reinterpret_cast<const uint2*>(Ql32 + gi);
    }

    int lr = tid >> 4;               // 0..15 base row
    int lc4 = (tid & 15) << 2;       // 0..60

    // prefetch tile 0
    uint2 khr[4], klr[4], vhr[4], vlr[4];
    #pragma unroll
    for (int i = 0; i < 4; i++) {
        int gi = ((lr + i*16)*HDIM + lc4) >> 1;
        khr[i] = *reinterpret_cast<const uint2*>(Kh32 + gi);
        klr[i] = *reinterpret_cast<const uint2*>(Kl32 + gi);
        vhr[i] = *reinterpret_cast<const uint2*>(Vh32 + gi);
        vlr[i] = *reinterpret_cast<const uint2*>(Vl32 + gi);
    }
    unsigned char mreg = (tid < 64) ? km[tid] : 0;

    __syncthreads();

    // ---- preload Q fragments ----
    uint32_t qh[4][4], ql[4][4];
    {
        int rl = warp*16 + grp;
        #pragma unroll
        for (int ks = 0; ks < 4; ks++) {
            int cc = thr4*2 + ks*16;
            qh[ks][0] = *(const uint32_t*)(sQh + rl*FPITCH + cc);
            qh[ks][1] = *(const uint32_t*)(sQh + (rl+8)*FPITCH + cc);
            qh[ks][2] = *(const uint32_t*)(sQh + rl*FPITCH + cc + 8);
            qh[ks][3] = *(const uint32_t*)(sQh + (rl+8)*FPITCH + cc + 8);
            ql[ks][0] = *(const uint32_t*)(sQl + rl*FPITCH + cc);
            ql[ks][1] = *(const uint32_t*)(sQl + (rl+8)*FPITCH + cc);
            ql[ks][2] = *(const uint32_t*)(sQl + rl*FPITCH + cc + 8);
            ql[ks][3] = *(const uint32_t*)(sQl + (rl+8)*FPITCH + cc + 8);
        }
    }

    int row0 = qbase + warp*16 + grp;
    int row1 = row0 + 8;

    float m0 = -1e30f, m1 = -1e30f, l0 = 0.f, l1 = 0.f;
    float o[8][4];
    #pragma unroll
    for (int j = 0; j < 8; j++)
        #pragma unroll
        for (int q = 0; q < 4; q++) o[j][q] = 0.f;

    const int ntiles = 2*qt + 2;
    for (int jt = 0; jt < ntiles; jt++) {
        int s0 = jt * 64;
        __syncthreads();
        // store prefetched K/V (copy; V scattered transposed)
        #pragma unroll
        for (int i = 0; i < 4; i++) {
            int r = lr + i*16;
            *reinterpret_cast<uint2*>(sKh + r*FPITCH + lc4) = khr[i];
            *reinterpret_cast<uint2*>(sKl + r*FPITCH + lc4) = klr[i];
            __nv_bfloat162 vh0 = *reinterpret_cast<__nv_bfloat162*>(&vhr[i].x);
            __nv_bfloat162 vh1 = *reinterpret_cast<__nv_bfloat162*>(&vhr[i].y);
            __nv_bfloat162 vl0 = *reinterpret_cast<__nv_bfloat162*>(&vlr[i].x);
            __nv_bfloat162 vl1 = *reinterpret_cast<__nv_bfloat162*>(&vlr[i].y);
            sVh[(lc4+0)*FPITCH + r] = vh0.x;
            sVh[(lc4+1)*FPITCH + r] = vh0.y;
            sVh[(lc4+2)*FPITCH + r] = vh1.x;
            sVh[(lc4+3)*FPITCH + r] = vh1.y;
            sVl[(lc4+0)*FPITCH + r] = vl0.x;
            sVl[(lc4+1)*FPITCH + r] = vl0.y;
            sVl[(lc4+2)*FPITCH + r] = vl1.x;
            sVl[(lc4+3)*FPITCH + r] = vl1.y;
        }
        if (tid < 64) mfs[tid] = mreg ? -1e30f : 0.0f;
        __syncthreads();

        // prefetch next tile while mmas run
        if (jt + 1 < ntiles) {
            #pragma unroll
            for (int i = 0; i < 4; i++) {
                int gi = ((s0 + 64 + lr + i*16)*HDIM + lc4) >> 1;
                khr[i] = *reinterpret_cast<const uint2*>(Kh32 + gi);
                klr[i] = *reinterpret_cast<const uint2*>(Kl32 + gi);
                vhr[i] = *reinterpret_cast<const uint2*>(Vh32 + gi);
                vlr[i] = *reinterpret_cast<const uint2*>(Vl32 + gi);
            }
            if (tid < 64) mreg = km[s0 + 64 + tid];
        }

        // ---- S = Q K^T ----
        float s[8][4];
        #pragma unroll
        for (int j = 0; j < 8; j++)
            #pragma unroll
            for (int q = 0; q < 4; q++) s[j][q] = 0.f;

        #pragma unroll
        for (int ks = 0; ks < 4; ks++) {
            int cc = thr4*2 + ks*16;
            #pragma unroll
            for (int j = 0; j < 8; j++) {
                int n = j*8 + grp;
                uint32_t bh0 = *(const uint32_t*)(sKh + n*FPITCH + cc);
                uint32_t bh1 = *(const uint32_t*)(sKh + n*FPITCH + cc + 8);
                uint32_t bl0 = *(const uint32_t*)(sKl + n*FPITCH + cc);
                uint32_t bl1 = *(const uint32_t*)(sKl + n*FPITCH + cc + 8);
                mma_bf16(s[j], qh[ks], bh0, bh1);
                mma_bf16(s[j], qh[ks], bl0, bl1);
                mma_bf16(s[j], ql[ks], bh0, bh1);
            }
        }

        // ---- scale + masks + online softmax ----
        bool diag = (jt >= 2*qt);
        float nm0 = m0, nm1 = m1;
        #pragma unroll
        for (int j = 0; j < 8; j++) {
            int cb = 8*j + 2*thr4;
            float f0 = mfs[cb], f1 = mfs[cb+1];
            float v00 = fmaf(s[j][0], 0.125f, f0);
            float v01 = fmaf(s[j][1], 0.125f, f1);
            float v10 = fmaf(s[j][2], 0.125f, f0);
            float v11 = fmaf(s[j][3], 0.125f, f1);
            if (diag) {
                int ca = s0 + cb;
                if (ca     > row0) v00 = -1e30f;
                if (ca + 1 > row0) v01 = -1e30f;
                if (ca     > row1) v10 = -1e30f;
                if (ca + 1 > row1) v11 = -1e30f;
            }
            s[j][0] = v00; s[j][1] = v01; s[j][2] = v10; s[j][3] = v11;
            nm0 = fmaxf(nm0, fmaxf(v00, v01));
            nm1 = fmaxf(nm1, fmaxf(v10, v11));
        }
        nm0 = fmaxf(nm0, __shfl_xor_sync(0xffffffffu, nm0, 1));
        nm0 = fmaxf(nm0, __shfl_xor_sync(0xffffffffu, nm0, 2));
        nm1 = fmaxf(nm1, __shfl_xor_sync(0xffffffffu, nm1, 1));
        nm1 = fmaxf(nm1, __shfl_xor_sync(0xffffffffu, nm1, 2));

        float c0 = __expf(m0 - nm0), c1 = __expf(m1 - nm1);
        m0 = nm0; m1 = nm1;

        float ls0 = 0.f, ls1 = 0.f;
        #pragma unroll
        for (int j = 0; j < 8; j++) {
            s[j][0] = __expf(s[j][0] - m0);
            s[j][1] = __expf(s[j][1] - m0);
            s[j][2] = __expf(s[j][2] - m1);
            s[j][3] = __expf(s[j][3] - m1);
            ls0 += s[j][0] + s[j][1];
            ls1 += s[j][2] + s[j][3];
        }
        ls0 += __shfl_xor_sync(0xffffffffu, ls0, 1);
        ls0 += __shfl_xor_sync(0xffffffffu, ls0, 2);
        ls1 += __shfl_xor_sync(0xffffffffu, ls1, 1);
        ls1 += __shfl_xor_sync(0xffffffffu, ls1, 2);
        l0 = l0*c0 + ls0;
        l1 = l1*c1 + ls1;

        #pragma unroll
        for (int j = 0; j < 8; j++) {
            o[j][0] *= c0; o[j][1] *= c0;
            o[j][2] *= c1; o[j][3] *= c1;
        }

        // ---- O += P V ----
        #pragma unroll
        for (int ks = 0; ks < 4; ks++) {
            uint32_t ph[4], pl[4];
            float* sa = s[2*ks];
            float* sb = s[2*ks + 1];
            pack2(sa[0], sa[1], ph[0], pl[0]);
            pack2(sa[2], sa[3], ph[1], pl[1]);
            pack2(sb[0], sb[1], ph[2], pl[2]);
            pack2(sb[2], sb[3], ph[3], pl[3]);
            int cc = thr4*2 + ks*16;
            #pragma unroll
            for (int j = 0; j < 8; j++) {
                int n = j*8 + grp;
                uint32_t vh0 = *(const uint32_t*)(sVh + n*FPITCH + cc);
                uint32_t vh1 = *(const uint32_t*)(sVh + n*FPITCH + cc + 8);
                uint32_t vl0 = *(const uint32_t*)(sVl + n*FPITCH + cc);
                uint32_t vl1 = *(const uint32_t*)(sVl + n*FPITCH + cc + 8);
                mma_bf16(o[j], ph, vh0, vh1);
                mma_bf16(o[j], ph, vl0, vl1);
                mma_bf16(o[j], pl, vh0, vh1);
            }
        }
    }

    // ---- epilogue: [B,T,E], pre-rounded to tf32 for gemm_out ----
    float inv0 = 1.f / l0, inv1 = 1.f / l1;
    float* O0 = g_ao + ((size_t)(b*SEQ) + row0)*EMBED + h*HDIM;
    float* O1 = g_ao + ((size_t)(b*SEQ) + row1)*EMBED + h*HDIM;
    #pragma unroll
    for (int j = 0; j < 8; j++) {
        int col = 8*j + 2*thr4;
        uint2 r0 = make_uint2(f2tf32(o[j][0]*inv0), f2tf32(o[j][1]*inv0));
        uint2 r1 = make_uint2(f2tf32(o[j][2]*inv1), f2tf32(o[j][3]*inv1));
        *reinterpret_cast<uint2*>(O0 + col) = r0;
        *reinterpret_cast<uint2*>(O1 + col) = r1;
    }
}

// ---------------------------------------------------------------------------
extern "C" void kernel_launch(void* const* d_in, const int* in_sizes, int n_in,
                              void* d_out, int out_size)
{
    const float* query = (const float*)d_in[0];
    const float* key   = (const float*)d_in[1];
    const float* value = (const float*)d_in[2];
    const unsigned char* kpm = (const unsigned char*)d_in[3];
    const float* bq = (const float*)d_in[5];
    const float* bk = (const float*)d_in[7];
    const float* bv = (const float*)d_in[9];
    const float* bo = (const float*)d_in[11];
    const float* Wq = (const float*)d_in[4];
    const float* Wk = (const float*)d_in[6];
    const float* Wv = (const float*)d_in[8];
    const float* Wo = (const float*)d_in[10];
    float* out = (float*)d_out;

    prepass<<<16384, 256>>>(query, key, value, Wq, Wk, Wv, Wo);

    cudaFuncSetAttribute(gemm_qkv, cudaFuncAttributeMaxDynamicSharedMemorySize, GEMM_SMEM);
    cudaFuncSetAttribute(gemm_out, cudaFuncAttributeMaxDynamicSharedMemorySize, GEMM_SMEM);

    dim3 gqkv(EMBED/128, MROWS/128, 3);   // (8, 32, 3)
    gemm_qkv<<<gqkv, 256, GEMM_SMEM>>>(bq, bk, bv);

    cudaFuncSetAttribute(flash_attn_mma, cudaFuncAttributeMaxDynamicSharedMemorySize, FLASH_SMEM);
    flash_attn_mma<<<dim3(SEQ/128, NHEAD, BATCH), 256, FLASH_SMEM>>>(kpm);

    dim3 gout(EMBED/128, MROWS/128);
    gemm_out<<<gout, 256, GEMM_SMEM>>>(bo, out);
}

// round 13
// speedup vs baseline: 1.1344x; 1.1344x over previous
#include <cuda_runtime.h>
#include <cuda_bf16.h>
#include <cstdint>

#define EMBED 1024
#define NHEAD 16
#define HDIM  64
#define BATCH 2
#define SEQ   2048
#define MROWS (BATCH*SEQ)   // 4096

// tf32-rounded copies of inputs / weights
__device__ float g_qc[MROWS*EMBED];
__device__ float g_kc[MROWS*EMBED];
__device__ float g_vc[MROWS*EMBED];
__device__ float g_w4[4*EMBED*EMBED];         // Wq | Wk | Wv | Wo
// bf16 hi/lo projections: Q,K in [B,H,T,D]; V in [B,H,D,T] (transposed!)
__device__ __nv_bfloat16 g_qh[BATCH*NHEAD*SEQ*HDIM];
__device__ __nv_bfloat16 g_ql[BATCH*NHEAD*SEQ*HDIM];
__device__ __nv_bfloat16 g_kh[BATCH*NHEAD*SEQ*HDIM];
__device__ __nv_bfloat16 g_kl[BATCH*NHEAD*SEQ*HDIM];
__device__ __nv_bfloat16 g_vh[BATCH*NHEAD*SEQ*HDIM];
__device__ __nv_bfloat16 g_vl[BATCH*NHEAD*SEQ*HDIM];
__device__ float g_maskf[BATCH*SEQ];          // 0 or -1e30
__device__ float g_ao[MROWS*EMBED];           // attention out, [B,T,E] (tf32-rounded)

__device__ __forceinline__ uint32_t f2tf32(float x) {
    uint32_t r;
    asm("cvt.rna.tf32.f32 %0, %1;" : "=r"(r) : "f"(x));
    return r;
}

__device__ __forceinline__ uint32_t smem_u32(const void* p) {
    uint32_t a;
    asm("{ .reg .u64 t; cvta.to.shared.u64 t, %1; cvt.u32.u64 %0, t; }" : "=r"(a) : "l"(p));
    return a;
}

// ---------------------------------------------------------------------------
// Prepass: tf32-round inputs + weights; float mask.
// ---------------------------------------------------------------------------
__global__ __launch_bounds__(256) void prepass(
    const float* __restrict__ q, const float* __restrict__ k, const float* __restrict__ v,
    const float* __restrict__ Wq, const float* __restrict__ Wk,
    const float* __restrict__ Wv, const float* __restrict__ Wo)
{
    int idx = blockIdx.x * 256 + threadIdx.x;       // float4 index
    const float* src; float* dst; int off;
    if (idx < 3145728) {
        int seg = idx >> 20;
        off = idx & 1048575;
        src = (seg == 0) ? q : (seg == 1) ? k : v;
        dst = (seg == 0) ? g_qc : (seg == 1) ? g_kc : g_vc;
    } else {
        int r = idx - 3145728;
        int seg = r >> 18;
        off = r & 262143;
        src = (seg == 0) ? Wq : (seg == 1) ? Wk : (seg == 2) ? Wv : Wo;
        dst = g_w4 + (size_t)seg * EMBED * EMBED;
    }
    float4 x = reinterpret_cast<const float4*>(src)[off];
    uint4 t = make_uint4(f2tf32(x.x), f2tf32(x.y), f2tf32(x.z), f2tf32(x.w));
    reinterpret_cast<uint4*>(dst)[off] = t;
}

__global__ __launch_bounds__(256) void mask_prep(const unsigned char* __restrict__ kpm)
{
    int i = blockIdx.x * 256 + threadIdx.x;
    if (i < BATCH*SEQ) g_maskf[i] = kpm[i] ? -1e30f : 0.0f;
}

// ---------------------------------------------------------------------------
// TF32 GEMM (R10-proven): 2-stage cp.async, BK=32, pitch 36, 2 CTAs/SM.
// mode: 0 = fp32 [M,E]; 1 = bf16 hi/lo [B,H,T,D]; 2 = bf16 hi/lo [B,H,D,T].
// ---------------------------------------------------------------------------
__device__ __forceinline__ void mma_tf32(float* c, const uint32_t* a,
                                         uint32_t b0, uint32_t b1) {
    asm volatile(
        "mma.sync.aligned.m16n8k8.row.col.f32.tf32.tf32.f32 "
        "{%0,%1,%2,%3}, {%4,%5,%6,%7}, {%8,%9}, {%0,%1,%2,%3};"
        : "+f"(c[0]), "+f"(c[1]), "+f"(c[2]), "+f"(c[3])
        : "r"(a[0]), "r"(a[1]), "r"(a[2]), "r"(a[3]), "r"(b0), "r"(b1));
}

#define GP 36
#define GA_WORDS (128*GP)
#define GSTAGE   (2*GA_WORDS)
#define GEMM_SMEM (2*GSTAGE*4)   // 73728

__device__ __forceinline__ void gemm_body(
    const float* __restrict__ A, const float* __restrict__ W,
    const float* __restrict__ bias, float* __restrict__ Cf,
    __nv_bfloat16* __restrict__ Ch, __nv_bfloat16* __restrict__ Cl,
    int m0, int n0, int mode)
{
    const int K = EMBED;
    extern __shared__ uint32_t gsm[];
    uint32_t sbase = smem_u32(gsm);

    int tid  = threadIdx.x;
    int lane = tid & 31;
    int warp = tid >> 5;
    int wm = warp >> 1, wn = warp & 1;
    int m0w = wm * 32, n0w = wn * 64;

    float c[2][8][4];
    #pragma unroll
    for (int mi = 0; mi < 2; mi++)
        #pragma unroll
        for (int ni = 0; ni < 8; ni++)
            #pragma unroll
            for (int q = 0; q < 4; q++) c[mi][ni][q] = 0.f;

    auto issue = [&](int k0, int s) {
        #pragma unroll
        for (int i = 0; i < 4; i++) {
            int idx = tid + i*256;
            int r = idx >> 3, c4 = (idx & 7) << 2;
            uint32_t da = sbase + (uint32_t)(s*GSTAGE + r*GP + c4) * 4u;
            const float* ga = A + (size_t)(m0 + r) * K + k0 + c4;
            asm volatile("cp.async.cg.shared.global [%0], [%1], 16;" :: "r"(da), "l"(ga));
            uint32_t dw = da + GA_WORDS * 4u;
            const float* gw = W + (size_t)(n0 + r) * K + k0 + c4;
            asm volatile("cp.async.cg.shared.global [%0], [%1], 16;" :: "r"(dw), "l"(gw));
        }
        asm volatile("cp.async.commit_group;" ::: "memory");
    };

    issue(0, 0);

    const int NCHUNK = K / 32;   // 32
    for (int ch = 0; ch < NCHUNK; ch++) {
        asm volatile("cp.async.wait_group 0;" ::: "memory");
        __syncthreads();
        if (ch + 1 < NCHUNK) issue((ch + 1) * 32, (ch + 1) & 1);

        const uint32_t* As = gsm + (ch & 1) * GSTAGE;
        const uint32_t* Ws = As + GA_WORDS;
        #pragma unroll
        for (int kk = 0; kk < 32; kk += 8) {
            int kb = kk + (lane & 3);
            uint32_t a[2][4];
            #pragma unroll
            for (int mi = 0; mi < 2; mi++) {
                int r = m0w + mi * 16 + (lane >> 2);
                a[mi][0] = As[r*GP + kb];
                a[mi][1] = As[(r + 8)*GP + kb];
                a[mi][2] = As[r*GP + kb + 4];
                a[mi][3] = As[(r + 8)*GP + kb + 4];
            }
            #pragma unroll
            for (int ni = 0; ni < 8; ni++) {
                int rn = n0w + ni * 8 + (lane >> 2);
                uint32_t b0 = Ws[rn*GP + kb];
                uint32_t b1 = Ws[rn*GP + kb + 4];
                mma_tf32(c[0][ni], a[0], b0, b1);
                mma_tf32(c[1][ni], a[1], b0, b1);
            }
        }
        __syncthreads();
    }

    #pragma unroll
    for (int mi = 0; mi < 2; mi++) {
        int rbase = m0 + m0w + mi * 16 + (lane >> 2);
        #pragma unroll
        for (int ni = 0; ni < 8; ni++) {
            int col = n0 + n0w + ni * 8 + 2 * (lane & 3);    // even
            float bv0 = bias[col], bv1 = bias[col + 1];
            #pragma unroll
            for (int half = 0; half < 2; half++) {
                int m = rbase + half * 8;
                float v0 = c[mi][ni][half * 2 + 0] + bv0;
                float v1 = c[mi][ni][half * 2 + 1] + bv1;
                if (mode == 0) {
                    Cf[(size_t)m * EMBED + col]     = v0;
                    Cf[(size_t)m * EMBED + col + 1] = v1;
                } else {
                    int bb = m >> 11, t = m & 2047;
                    int hh = col >> 6, d = col & 63;
                    __nv_bfloat16 h0 = __float2bfloat16(v0), h1 = __float2bfloat16(v1);
                    __nv_bfloat16 l0v = __float2bfloat16(v0 - __bfloat162float(h0));
                    __nv_bfloat16 l1v = __float2bfloat16(v1 - __bfloat162float(h1));
                    if (mode == 1) {
                        size_t base = (((size_t)(bb * NHEAD + hh)) * SEQ + t) * HDIM + d;
                        __nv_bfloat162 hp; hp.x = h0; hp.y = h1;
                        __nv_bfloat162 lp; lp.x = l0v; lp.y = l1v;
                        reinterpret_cast<uint32_t*>(Ch)[base >> 1] = *reinterpret_cast<uint32_t*>(&hp);
                        reinterpret_cast<uint32_t*>(Cl)[base >> 1] = *reinterpret_cast<uint32_t*>(&lp);
                    } else {   // mode 2: transposed [B,H,D,T]
                        size_t o0 = (((size_t)(bb * NHEAD + hh)) * HDIM + d) * SEQ + t;
                        Ch[o0]       = h0;
                        Ch[o0 + SEQ] = h1;
                        Cl[o0]       = l0v;
                        Cl[o0 + SEQ] = l1v;
                    }
                }
            }
        }
    }
}

__global__ __launch_bounds__(256) void gemm_qkv(
    const float* __restrict__ bq, const float* __restrict__ bk, const float* __restrict__ bv)
{
    int z = blockIdx.z;
    const float* A = (z == 0) ? g_qc : (z == 1) ? g_kc : g_vc;
    const float* W = g_w4 + (size_t)z * EMBED * EMBED;
    const float* B = (z == 0) ? bq : (z == 1) ? bk : bv;
    __nv_bfloat16* Ch = (z == 0) ? g_qh : (z == 1) ? g_kh : g_vh;
    __nv_bfloat16* Cl = (z == 0) ? g_ql : (z == 1) ? g_kl : g_vl;
    gemm_body(A, W, B, nullptr, Ch, Cl, blockIdx.y * 128, blockIdx.x * 128,
              (z == 2) ? 2 : 1);
}

__global__ __launch_bounds__(256) void gemm_out(
    const float* __restrict__ bias, float* __restrict__ C)
{
    gemm_body(g_ao, g_w4 + (size_t)3 * EMBED * EMBED, bias, C,
              nullptr, nullptr, blockIdx.y * 128, blockIdx.x * 128, 0);
}

// ---------------------------------------------------------------------------
// Flash attention: bf16 split mma core (unchanged numerics); K/V/mask staged
// via 2-stage cp.async pipeline (V pre-transposed in global), 1 barrier/tile.
// ---------------------------------------------------------------------------
__device__ __forceinline__ void mma_bf16(float* c, const uint32_t* a,
                                         uint32_t b0, uint32_t b1) {
    asm volatile(
        "mma.sync.aligned.m16n8k16.row.col.f32.bf16.bf16.f32 "
        "{%0,%1,%2,%3}, {%4,%5,%6,%7}, {%8,%9}, {%0,%1,%2,%3};"
        : "+f"(c[0]), "+f"(c[1]), "+f"(c[2]), "+f"(c[3])
        : "r"(a[0]), "r"(a[1]), "r"(a[2]), "r"(a[3]), "r"(b0), "r"(b1));
}

__device__ __forceinline__ void pack2(float x, float y, uint32_t& hi, uint32_t& lo) {
    __nv_bfloat16 hx = __float2bfloat16(x), hy = __float2bfloat16(y);
    __nv_bfloat162 h2; h2.x = hx; h2.y = hy;
    hi = *reinterpret_cast<uint32_t*>(&h2);
    __nv_bfloat162 l2;
    l2.x = __float2bfloat16(x - __bfloat162float(hx));
    l2.y = __float2bfloat16(y - __bfloat162float(hy));
    lo = *reinterpret_cast<uint32_t*>(&l2);
}

#define FPITCH 72                 // bf16 elems per row: 128B data + 16B pad
#define FSM_Q        0
#define FSM_STAGE0   36864        // 128 rows * 144B * 2 (Qh+Ql)
#define FSM_STAGE_SZ 36864        // Kh,Kl,Vh,Vl: 4 * 64 * 144B
#define FSM_REG      9216         // one region
#define FSM_MASK     (FSM_STAGE0 + 2*FSM_STAGE_SZ)   // 110592
#define FLASH_SMEM   (FSM_MASK + 2*256)              // 111104

__global__ __launch_bounds__(256, 1) void flash_attn_mma()
{
    extern __shared__ __align__(16) char smraw[];
    __nv_bfloat16* sQh = (__nv_bfloat16*)smraw;
    __nv_bfloat16* sQl = sQh + 128*FPITCH;
    uint32_t sb = smem_u32(smraw);

    int tid  = threadIdx.x;
    int lane = tid & 31, warp = tid >> 5;
    int grp  = lane >> 2, thr4 = lane & 3;
    int qt = (int)gridDim.x - 1 - (int)blockIdx.x;   // heavy tiles first
    int h = blockIdx.y, b = blockIdx.z;
    int qbase = qt * 128;

    size_t headoff = ((size_t)(b*NHEAD + h))*SEQ*HDIM;
    const uint32_t* Qh32 = (const uint32_t*)g_qh + (headoff + (size_t)qbase*HDIM)/2;
    const uint32_t* Ql32 = (const uint32_t*)g_ql + (headoff + (size_t)qbase*HDIM)/2;
    const char* khg = (const char*)g_kh + headoff*2;
    const char* klg = (const char*)g_kl + headoff*2;
    const char* vhg = (const char*)g_vh + headoff*2;   // [D][T] layout
    const char* vlg = (const char*)g_vl + headoff*2;
    const char* mfg = (const char*)(g_maskf + (size_t)b*SEQ);

    const int ntiles = 2*qt + 2;

    // cp.async stage issue: K rows [s][d] 128B; V rows [d][t-window] 128B; mask 256B
    auto issue = [&](int jt) {
        int st = jt & 1;
        int s0 = jt * 64;
        uint32_t base = sb + FSM_STAGE0 + st*FSM_STAGE_SZ;
        #pragma unroll
        for (int i = 0; i < 2; i++) {
            int c = tid + i*256;            // 0..511
            int row = c >> 3;
            int o16 = (c & 7) * 16;
            uint32_t doff = (uint32_t)(row*144 + o16);
            const char* ksrc = khg + (size_t)(s0 + row)*128 + o16;
            asm volatile("cp.async.cg.shared.global [%0], [%1], 16;" :: "r"(base + doff), "l"(ksrc));
            const char* ksrc2 = klg + (size_t)(s0 + row)*128 + o16;
            asm volatile("cp.async.cg.shared.global [%0], [%1], 16;" :: "r"(base + FSM_REG + doff), "l"(ksrc2));
            const char* vsrc = vhg + (size_t)row*(SEQ*2) + s0*2 + o16;
            asm volatile("cp.async.cg.shared.global [%0], [%1], 16;" :: "r"(base + 2*FSM_REG + doff), "l"(vsrc));
            const char* vsrc2 = vlg + (size_t)row*(SEQ*2) + s0*2 + o16;
            asm volatile("cp.async.cg.shared.global [%0], [%1], 16;" :: "r"(base + 3*FSM_REG + doff), "l"(vsrc2));
        }
        if (tid < 16) {
            uint32_t dm = sb + FSM_MASK + st*256 + tid*16;
            const char* ms = mfg + (size_t)s0*4 + tid*16;
            asm volatile("cp.async.cg.shared.global [%0], [%1], 16;" :: "r"(dm), "l"(ms));
        }
        asm volatile("cp.async.commit_group;" ::: "memory");
    };

    issue(0);

    // ---- stage Q (pure copy, once) ----
    #pragma unroll
    for (int i = 0; i < 8; i++) {
        int e = tid + i*256;
        int r = e >> 4, c4 = (e & 15) << 2;
        int gi = (r*HDIM + c4) >> 1;
        *reinterpret_cast<uint2*>(sQh + r*FPITCH + c4) = *reinterpret_cast<const uint2*>(Qh32 + gi);
        *reinterpret_cast<uint2*>(sQl + r*FPITCH + c4) = *reinterpret_cast<const uint2*>(Ql32 + gi);
    }
    __syncthreads();

    // ---- preload Q fragments ----
    uint32_t qh[4][4], ql[4][4];
    {
        int rl = warp*16 + grp;
        #pragma unroll
        for (int ks = 0; ks < 4; ks++) {
            int cc = thr4*2 + ks*16;
            qh[ks][0] = *(const uint32_t*)(sQh + rl*FPITCH + cc);
            qh[ks][1] = *(const uint32_t*)(sQh + (rl+8)*FPITCH + cc);
            qh[ks][2] = *(const uint32_t*)(sQh + rl*FPITCH + cc + 8);
            qh[ks][3] = *(const uint32_t*)(sQh + (rl+8)*FPITCH + cc + 8);
            ql[ks][0] = *(const uint32_t*)(sQl + rl*FPITCH + cc);
            ql[ks][1] = *(const uint32_t*)(sQl + (rl+8)*FPITCH + cc);
            ql[ks][2] = *(const uint32_t*)(sQl + rl*FPITCH + cc + 8);
            ql[ks][3] = *(const uint32_t*)(sQl + (rl+8)*FPITCH + cc + 8);
        }
    }

    int row0 = qbase + warp*16 + grp;
    int row1 = row0 + 8;

    float m0 = -1e30f, m1 = -1e30f, l0 = 0.f, l1 = 0.f;
    float o[8][4];
    #pragma unroll
    for (int j = 0; j < 8; j++)
        #pragma unroll
        for (int q = 0; q < 4; q++) o[j][q] = 0.f;

    for (int jt = 0; jt < ntiles; jt++) {
        int s0 = jt * 64;
        int st = jt & 1;
        asm volatile("cp.async.wait_group 0;" ::: "memory");
        __syncthreads();                       // stage st visible; prev compute done
        if (jt + 1 < ntiles) issue(jt + 1);    // overlaps with this tile's mmas

        __nv_bfloat16* sKh = (__nv_bfloat16*)(smraw + FSM_STAGE0 + st*FSM_STAGE_SZ);
        __nv_bfloat16* sKl = sKh + FSM_REG/2;
        __nv_bfloat16* sVh = sKh + FSM_REG;       // 2*FSM_REG bytes => /2 elems
        __nv_bfloat16* sVl = sKh + 3*FSM_REG/2;
        float* mfs = (float*)(smraw + FSM_MASK + st*256);

        // ---- S = Q K^T ----
        float s[8][4];
        #pragma unroll
        for (int j = 0; j < 8; j++)
            #pragma unroll
            for (int q = 0; q < 4; q++) s[j][q] = 0.f;

        #pragma unroll
        for (int ks = 0; ks < 4; ks++) {
            int cc = thr4*2 + ks*16;
            #pragma unroll
            for (int j = 0; j < 8; j++) {
                int n = j*8 + grp;
                uint32_t bh0 = *(const uint32_t*)(sKh + n*FPITCH + cc);
                uint32_t bh1 = *(const uint32_t*)(sKh + n*FPITCH + cc + 8);
                uint32_t bl0 = *(const uint32_t*)(sKl + n*FPITCH + cc);
                uint32_t bl1 = *(const uint32_t*)(sKl + n*FPITCH + cc + 8);
                mma_bf16(s[j], qh[ks], bh0, bh1);
                mma_bf16(s[j], qh[ks], bl0, bl1);
                mma_bf16(s[j], ql[ks], bh0, bh1);
            }
        }

        // ---- scale + masks + online softmax ----
        bool diag = (jt >= 2*qt);
        float nm0 = m0, nm1 = m1;
        #pragma unroll
        for (int j = 0; j < 8; j++) {
            int cb = 8*j + 2*thr4;
            float f0 = mfs[cb], f1 = mfs[cb+1];
            float v00 = fmaf(s[j][0], 0.125f, f0);
            float v01 = fmaf(s[j][1], 0.125f, f1);
            float v10 = fmaf(s[j][2], 0.125f, f0);
            float v11 = fmaf(s[j][3], 0.125f, f1);
            if (diag) {
                int ca = s0 + cb;
                if (ca     > row0) v00 = -1e30f;
                if (ca + 1 > row0) v01 = -1e30f;
                if (ca     > row1) v10 = -1e30f;
                if (ca + 1 > row1) v11 = -1e30f;
            }
            s[j][0] = v00; s[j][1] = v01; s[j][2] = v10; s[j][3] = v11;
            nm0 = fmaxf(nm0, fmaxf(v00, v01));
            nm1 = fmaxf(nm1, fmaxf(v10, v11));
        }
        nm0 = fmaxf(nm0, __shfl_xor_sync(0xffffffffu, nm0, 1));
        nm0 = fmaxf(nm0, __shfl_xor_sync(0xffffffffu, nm0, 2));
        nm1 = fmaxf(nm1, __shfl_xor_sync(0xffffffffu, nm1, 1));
        nm1 = fmaxf(nm1, __shfl_xor_sync(0xffffffffu, nm1, 2));

        float c0 = __expf(m0 - nm0), c1 = __expf(m1 - nm1);
        m0 = nm0; m1 = nm1;

        float ls0 = 0.f, ls1 = 0.f;
        #pragma unroll
        for (int j = 0; j < 8; j++) {
            s[j][0] = __expf(s[j][0] - m0);
            s[j][1] = __expf(s[j][1] - m0);
            s[j][2] = __expf(s[j][2] - m1);
            s[j][3] = __expf(s[j][3] - m1);
            ls0 += s[j][0] + s[j][1];
            ls1 += s[j][2] + s[j][3];
        }
        ls0 += __shfl_xor_sync(0xffffffffu, ls0, 1);
        ls0 += __shfl_xor_sync(0xffffffffu, ls0, 2);
        ls1 += __shfl_xor_sync(0xffffffffu, ls1, 1);
        ls1 += __shfl_xor_sync(0xffffffffu, ls1, 2);
        l0 = l0*c0 + ls0;
        l1 = l1*c1 + ls1;

        #pragma unroll
        for (int j = 0; j < 8; j++) {
            o[j][0] *= c0; o[j][1] *= c0;
            o[j][2] *= c1; o[j][3] *= c1;
        }

        // ---- O += P V ----
        #pragma unroll
        for (int ks = 0; ks < 4; ks++) {
            uint32_t ph[4], pl[4];
            float* sa = s[2*ks];
            float* sbp = s[2*ks + 1];
            pack2(sa[0], sa[1], ph[0], pl[0]);
            pack2(sa[2], sa[3], ph[1], pl[1]);
            pack2(sbp[0], sbp[1], ph[2], pl[2]);
            pack2(sbp[2], sbp[3], ph[3], pl[3]);
            int cc = thr4*2 + ks*16;
            #pragma unroll
            for (int j = 0; j < 8; j++) {
                int n = j*8 + grp;
                uint32_t vh0 = *(const uint32_t*)(sVh + n*FPITCH + cc);
                uint32_t vh1 = *(const uint32_t*)(sVh + n*FPITCH + cc + 8);
                uint32_t vl0 = *(const uint32_t*)(sVl + n*FPITCH + cc);
                uint32_t vl1 = *(const uint32_t*)(sVl + n*FPITCH + cc + 8);
                mma_bf16(o[j], ph, vh0, vh1);
                mma_bf16(o[j], ph, vl0, vl1);
                mma_bf16(o[j], pl, vh0, vh1);
            }
        }
    }

    // ---- epilogue: [B,T,E], pre-rounded to tf32 for gemm_out ----
    float inv0 = 1.f / l0, inv1 = 1.f / l1;
    float* O0 = g_ao + ((size_t)(b*SEQ) + row0)*EMBED + h*HDIM;
    float* O1 = g_ao + ((size_t)(b*SEQ) + row1)*EMBED + h*HDIM;
    #pragma unroll
    for (int j = 0; j < 8; j++) {
        int col = 8*j + 2*thr4;
        uint2 r0 = make_uint2(f2tf32(o[j][0]*inv0), f2tf32(o[j][1]*inv0));
        uint2 r1 = make_uint2(f2tf32(o[j][2]*inv1), f2tf32(o[j][3]*inv1));
        *reinterpret_cast<uint2*>(O0 + col) = r0;
        *reinterpret_cast<uint2*>(O1 + col) = r1;
    }
}

// ---------------------------------------------------------------------------
extern "C" void kernel_launch(void* const* d_in, const int* in_sizes, int n_in,
                              void* d_out, int out_size)
{
    const float* query = (const float*)d_in[0];
    const float* key   = (const float*)d_in[1];
    const float* value = (const float*)d_in[2];
    const unsigned char* kpm = (const unsigned char*)d_in[3];
    const float* Wq = (const float*)d_in[4];
    const float* bq = (const float*)d_in[5];
    const float* Wk = (const float*)d_in[6];
    const float* bk = (const float*)d_in[7];
    const float* Wv = (const float*)d_in[8];
    const float* bv = (const float*)d_in[9];
    const float* Wo = (const float*)d_in[10];
    const float* bo = (const float*)d_in[11];
    float* out = (float*)d_out;

    prepass<<<16384, 256>>>(query, key, value, Wq, Wk, Wv, Wo);
    mask_prep<<<16, 256>>>(kpm);

    cudaFuncSetAttribute(gemm_qkv, cudaFuncAttributeMaxDynamicSharedMemorySize, GEMM_SMEM);
    cudaFuncSetAttribute(gemm_out, cudaFuncAttributeMaxDynamicSharedMemorySize, GEMM_SMEM);

    dim3 gqkv(EMBED/128, MROWS/128, 3);   // (8, 32, 3)
    gemm_qkv<<<gqkv, 256, GEMM_SMEM>>>(bq, bk, bv);

    cudaFuncSetAttribute(flash_attn_mma, cudaFuncAttributeMaxDynamicSharedMemorySize, FLASH_SMEM);
    flash_attn_mma<<<dim3(SEQ/128, NHEAD, BATCH), 256, FLASH_SMEM>>>();

    dim3 gout(EMBED/128, MROWS/128);
    gemm_out<<<gout, 256, GEMM_SMEM>>>(bo, out);
}

// round 14
// speedup vs baseline: 1.2065x; 1.0636x over previous
#include <cuda_runtime.h>
#include <cuda_fp16.h>
#include <cstdint>

#define EMBED 1024
#define NHEAD 16
#define HDIM  64
#define BATCH 2
#define SEQ   2048
#define MROWS (BATCH*SEQ)   // 4096

// tf32-rounded copies of inputs / weights
__device__ float g_qc[MROWS*EMBED];
__device__ float g_kc[MROWS*EMBED];
__device__ float g_vc[MROWS*EMBED];
__device__ float g_w4[4*EMBED*EMBED];         // Wq | Wk | Wv | Wo
// fp16 hi/lo projections: Q,K in [B,H,T,D]; V in [B,H,D,T] (transposed)
__device__ __half g_qh[BATCH*NHEAD*SEQ*HDIM];
__device__ __half g_ql[BATCH*NHEAD*SEQ*HDIM];
__device__ __half g_kh[BATCH*NHEAD*SEQ*HDIM];
__device__ __half g_kl[BATCH*NHEAD*SEQ*HDIM];
__device__ __half g_vh[BATCH*NHEAD*SEQ*HDIM];
__device__ __half g_vl[BATCH*NHEAD*SEQ*HDIM];
__device__ float g_maskf[BATCH*SEQ];          // 0 or -1e30
__device__ float g_ao[MROWS*EMBED];           // attention out, [B,T,E] (tf32-rounded)

__device__ __forceinline__ uint32_t f2tf32(float x) {
    uint32_t r;
    asm("cvt.rna.tf32.f32 %0, %1;" : "=r"(r) : "f"(x));
    return r;
}

__device__ __forceinline__ uint32_t smem_u32(const void* p) {
    uint32_t a;
    asm("{ .reg .u64 t; cvta.to.shared.u64 t, %1; cvt.u32.u64 %0, t; }" : "=r"(a) : "l"(p));
    return a;
}

// ---------------------------------------------------------------------------
// Prepass: tf32-round inputs + weights; float mask.
// ---------------------------------------------------------------------------
__global__ __launch_bounds__(256) void prepass(
    const float* __restrict__ q, const float* __restrict__ k, const float* __restrict__ v,
    const float* __restrict__ Wq, const float* __restrict__ Wk,
    const float* __restrict__ Wv, const float* __restrict__ Wo)
{
    int idx = blockIdx.x * 256 + threadIdx.x;       // float4 index
    const float* src; float* dst; int off;
    if (idx < 3145728) {
        int seg = idx >> 20;
        off = idx & 1048575;
        src = (seg == 0) ? q : (seg == 1) ? k : v;
        dst = (seg == 0) ? g_qc : (seg == 1) ? g_kc : g_vc;
    } else {
        int r = idx - 3145728;
        int seg = r >> 18;
        off = r & 262143;
        src = (seg == 0) ? Wq : (seg == 1) ? Wk : (seg == 2) ? Wv : Wo;
        dst = g_w4 + (size_t)seg * EMBED * EMBED;
    }
    float4 x = reinterpret_cast<const float4*>(src)[off];
    uint4 t = make_uint4(f2tf32(x.x), f2tf32(x.y), f2tf32(x.z), f2tf32(x.w));
    reinterpret_cast<uint4*>(dst)[off] = t;
}

__global__ __launch_bounds__(256) void mask_prep(const unsigned char* __restrict__ kpm)
{
    int i = blockIdx.x * 256 + threadIdx.x;
    if (i < BATCH*SEQ) g_maskf[i] = kpm[i] ? -1e30f : 0.0f;
}

// ---------------------------------------------------------------------------
// TF32 GEMM (R10-proven): 2-stage cp.async, BK=32, pitch 36, 2 CTAs/SM.
// mode: 0 = fp32 [M,E]; 1 = fp16 hi/lo [B,H,T,D]; 2 = fp16 hi/lo [B,H,D,T].
// ---------------------------------------------------------------------------
__device__ __forceinline__ void mma_tf32(float* c, const uint32_t* a,
                                         uint32_t b0, uint32_t b1) {
    asm volatile(
        "mma.sync.aligned.m16n8k8.row.col.f32.tf32.tf32.f32 "
        "{%0,%1,%2,%3}, {%4,%5,%6,%7}, {%8,%9}, {%0,%1,%2,%3};"
        : "+f"(c[0]), "+f"(c[1]), "+f"(c[2]), "+f"(c[3])
        : "r"(a[0]), "r"(a[1]), "r"(a[2]), "r"(a[3]), "r"(b0), "r"(b1));
}

#define GP 36
#define GA_WORDS (128*GP)
#define GSTAGE   (2*GA_WORDS)
#define GEMM_SMEM (2*GSTAGE*4)   // 73728

__device__ __forceinline__ void gemm_body(
    const float* __restrict__ A, const float* __restrict__ W,
    const float* __restrict__ bias, float* __restrict__ Cf,
    __half* __restrict__ Ch, __half* __restrict__ Cl,
    int m0, int n0, int mode)
{
    const int K = EMBED;
    extern __shared__ uint32_t gsm[];
    uint32_t sbase = smem_u32(gsm);

    int tid  = threadIdx.x;
    int lane = tid & 31;
    int warp = tid >> 5;
    int wm = warp >> 1, wn = warp & 1;
    int m0w = wm * 32, n0w = wn * 64;

    float c[2][8][4];
    #pragma unroll
    for (int mi = 0; mi < 2; mi++)
        #pragma unroll
        for (int ni = 0; ni < 8; ni++)
            #pragma unroll
            for (int q = 0; q < 4; q++) c[mi][ni][q] = 0.f;

    auto issue = [&](int k0, int s) {
        #pragma unroll
        for (int i = 0; i < 4; i++) {
            int idx = tid + i*256;
            int r = idx >> 3, c4 = (idx & 7) << 2;
            uint32_t da = sbase + (uint32_t)(s*GSTAGE + r*GP + c4) * 4u;
            const float* ga = A + (size_t)(m0 + r) * K + k0 + c4;
            asm volatile("cp.async.cg.shared.global [%0], [%1], 16;" :: "r"(da), "l"(ga));
            uint32_t dw = da + GA_WORDS * 4u;
            const float* gw = W + (size_t)(n0 + r) * K + k0 + c4;
            asm volatile("cp.async.cg.shared.global [%0], [%1], 16;" :: "r"(dw), "l"(gw));
        }
        asm volatile("cp.async.commit_group;" ::: "memory");
    };

    issue(0, 0);

    const int NCHUNK = K / 32;   // 32
    for (int ch = 0; ch < NCHUNK; ch++) {
        asm volatile("cp.async.wait_group 0;" ::: "memory");
        __syncthreads();
        if (ch + 1 < NCHUNK) issue((ch + 1) * 32, (ch + 1) & 1);

        const uint32_t* As = gsm + (ch & 1) * GSTAGE;
        const uint32_t* Ws = As + GA_WORDS;
        #pragma unroll
        for (int kk = 0; kk < 32; kk += 8) {
            int kb = kk + (lane & 3);
            uint32_t a[2][4];
            #pragma unroll
            for (int mi = 0; mi < 2; mi++) {
                int r = m0w + mi * 16 + (lane >> 2);
                a[mi][0] = As[r*GP + kb];
                a[mi][1] = As[(r + 8)*GP + kb];
                a[mi][2] = As[r*GP + kb + 4];
                a[mi][3] = As[(r + 8)*GP + kb + 4];
            }
            #pragma unroll
            for (int ni = 0; ni < 8; ni++) {
                int rn = n0w + ni * 8 + (lane >> 2);
                uint32_t b0 = Ws[rn*GP + kb];
                uint32_t b1 = Ws[rn*GP + kb + 4];
                mma_tf32(c[0][ni], a[0], b0, b1);
                mma_tf32(c[1][ni], a[1], b0, b1);
            }
        }
        __syncthreads();
    }

    #pragma unroll
    for (int mi = 0; mi < 2; mi++) {
        int rbase = m0 + m0w + mi * 16 + (lane >> 2);
        #pragma unroll
        for (int ni = 0; ni < 8; ni++) {
            int col = n0 + n0w + ni * 8 + 2 * (lane & 3);    // even
            float bv0 = bias[col], bv1 = bias[col + 1];
            #pragma unroll
            for (int half = 0; half < 2; half++) {
                int m = rbase + half * 8;
                float v0 = c[mi][ni][half * 2 + 0] + bv0;
                float v1 = c[mi][ni][half * 2 + 1] + bv1;
                if (mode == 0) {
                    Cf[(size_t)m * EMBED + col]     = v0;
                    Cf[(size_t)m * EMBED + col + 1] = v1;
                } else {
                    int bb = m >> 11, t = m & 2047;
                    int hh = col >> 6, d = col & 63;
                    __half h0 = __float2half(v0), h1 = __float2half(v1);
                    __half l0v = __float2half(v0 - __half2float(h0));
                    __half l1v = __float2half(v1 - __half2float(h1));
                    if (mode == 1) {
                        size_t base = (((size_t)(bb * NHEAD + hh)) * SEQ + t) * HDIM + d;
                        __half2 hp = __halves2half2(h0, h1);
                        __half2 lp = __halves2half2(l0v, l1v);
                        reinterpret_cast<uint32_t*>(Ch)[base >> 1] = *reinterpret_cast<uint32_t*>(&hp);
                        reinterpret_cast<uint32_t*>(Cl)[base >> 1] = *reinterpret_cast<uint32_t*>(&lp);
                    } else {   // mode 2: transposed [B,H,D,T]
                        size_t o0 = (((size_t)(bb * NHEAD + hh)) * HDIM + d) * SEQ + t;
                        Ch[o0]       = h0;
                        Ch[o0 + SEQ] = h1;
                        Cl[o0]       = l0v;
                        Cl[o0 + SEQ] = l1v;
                    }
                }
            }
        }
    }
}

__global__ __launch_bounds__(256) void gemm_qkv(
    const float* __restrict__ bq, const float* __restrict__ bk, const float* __restrict__ bv)
{
    int z = blockIdx.z;
    const float* A = (z == 0) ? g_qc : (z == 1) ? g_kc : g_vc;
    const float* W = g_w4 + (size_t)z * EMBED * EMBED;
    const float* B = (z == 0) ? bq : (z == 1) ? bk : bv;
    __half* Ch = (z == 0) ? g_qh : (z == 1) ? g_kh : g_vh;
    __half* Cl = (z == 0) ? g_ql : (z == 1) ? g_kl : g_vl;
    gemm_body(A, W, B, nullptr, Ch, Cl, blockIdx.y * 128, blockIdx.x * 128,
              (z == 2) ? 2 : 1);
}

__global__ __launch_bounds__(256) void gemm_out(
    const float* __restrict__ bias, float* __restrict__ C)
{
    gemm_body(g_ao, g_w4 + (size_t)3 * EMBED * EMBED, bias, C,
              nullptr, nullptr, blockIdx.y * 128, blockIdx.x * 128, 0);
}

// ---------------------------------------------------------------------------
// Flash attention: fp16 split mma; exp via ex2.approx.f16x2 (output = packed
// P operand); l via ones-mma; 2-stage cp.async staging (V pre-transposed).
// ---------------------------------------------------------------------------
__device__ __forceinline__ void mma_f16(float* c, const uint32_t* a,
                                        uint32_t b0, uint32_t b1) {
    asm volatile(
        "mma.sync.aligned.m16n8k16.row.col.f32.f16.f16.f32 "
        "{%0,%1,%2,%3}, {%4,%5,%6,%7}, {%8,%9}, {%0,%1,%2,%3};"
        : "+f"(c[0]), "+f"(c[1]), "+f"(c[2]), "+f"(c[3])
        : "r"(a[0]), "r"(a[1]), "r"(a[2]), "r"(a[3]), "r"(b0), "r"(b1));
}

#define FPITCH 72                 // fp16 elems per row: 128B data + 16B pad
#define FSM_STAGE0   36864        // Q region: 128 rows * 144B * 2 (Qh+Ql)
#define FSM_STAGE_SZ 36864        // Kh,Kl,Vh,Vl: 4 * 64 * 144B
#define FSM_REG      9216
#define FSM_MASK     (FSM_STAGE0 + 2*FSM_STAGE_SZ)   // 110592
#define FLASH_SMEM   (FSM_MASK + 2*256)              // 111104

__global__ __launch_bounds__(256, 1) void flash_attn_mma()
{
    extern __shared__ __align__(16) char smraw[];
    __half* sQh = (__half*)smraw;
    __half* sQl = sQh + 128*FPITCH;
    uint32_t sb = smem_u32(smraw);

    int tid  = threadIdx.x;
    int lane = tid & 31, warp = tid >> 5;
    int grp  = lane >> 2, thr4 = lane & 3;
    int qt = (int)gridDim.x - 1 - (int)blockIdx.x;   // heavy tiles first
    int h = blockIdx.y, b = blockIdx.z;
    int qbase = qt * 128;

    size_t headoff = ((size_t)(b*NHEAD + h))*SEQ*HDIM;
    const uint32_t* Qh32 = (const uint32_t*)g_qh + (headoff + (size_t)qbase*HDIM)/2;
    const uint32_t* Ql32 = (const uint32_t*)g_ql + (headoff + (size_t)qbase*HDIM)/2;
    const char* khg = (const char*)g_kh + headoff*2;
    const char* klg = (const char*)g_kl + headoff*2;
    const char* vhg = (const char*)g_vh + headoff*2;   // [D][T] layout
    const char* vlg = (const char*)g_vl + headoff*2;
    const char* mfg = (const char*)(g_maskf + (size_t)b*SEQ);

    const int ntiles = 2*qt + 2;

    auto issue = [&](int jt) {
        int st = jt & 1;
        int s0 = jt * 64;
        uint32_t base = sb + FSM_STAGE0 + st*FSM_STAGE_SZ;
        #pragma unroll
        for (int i = 0; i < 2; i++) {
            int c = tid + i*256;            // 0..511
            int row = c >> 3;
            int o16 = (c & 7) * 16;
            uint32_t doff = (uint32_t)(row*144 + o16);
            const char* ksrc = khg + (size_t)(s0 + row)*128 + o16;
            asm volatile("cp.async.cg.shared.global [%0], [%1], 16;" :: "r"(base + doff), "l"(ksrc));
            const char* ksrc2 = klg + (size_t)(s0 + row)*128 + o16;
            asm volatile("cp.async.cg.shared.global [%0], [%1], 16;" :: "r"(base + FSM_REG + doff), "l"(ksrc2));
            const char* vsrc = vhg + (size_t)row*(SEQ*2) + s0*2 + o16;
            asm volatile("cp.async.cg.shared.global [%0], [%1], 16;" :: "r"(base + 2*FSM_REG + doff), "l"(vsrc));
            const char* vsrc2 = vlg + (size_t)row*(SEQ*2) + s0*2 + o16;
            asm volatile("cp.async.cg.shared.global [%0], [%1], 16;" :: "r"(base + 3*FSM_REG + doff), "l"(vsrc2));
        }
        if (tid < 16) {
            uint32_t dm = sb + FSM_MASK + st*256 + tid*16;
            const char* ms = mfg + (size_t)s0*4 + tid*16;
            asm volatile("cp.async.cg.shared.global [%0], [%1], 16;" :: "r"(dm), "l"(ms));
        }
        asm volatile("cp.async.commit_group;" ::: "memory");
    };

    issue(0);

    // ---- stage Q (pure copy, once) ----
    #pragma unroll
    for (int i = 0; i < 8; i++) {
        int e = tid + i*256;
        int r = e >> 4, c4 = (e & 15) << 2;
        int gi = (r*HDIM + c4) >> 1;
        *reinterpret_cast<uint2*>(sQh + r*FPITCH + c4) = *reinterpret_cast<const uint2*>(Qh32 + gi);
        *reinterpret_cast<uint2*>(sQl + r*FPITCH + c4) = *reinterpret_cast<const uint2*>(Ql32 + gi);
    }
    __syncthreads();

    // ---- preload Q fragments ----
    uint32_t qh[4][4], ql[4][4];
    {
        int rl = warp*16 + grp;
        #pragma unroll
        for (int ks = 0; ks < 4; ks++) {
            int cc = thr4*2 + ks*16;
            qh[ks][0] = *(const uint32_t*)(sQh + rl*FPITCH + cc);
            qh[ks][1] = *(const uint32_t*)(sQh + (rl+8)*FPITCH + cc);
            qh[ks][2] = *(const uint32_t*)(sQh + rl*FPITCH + cc + 8);
            qh[ks][3] = *(const uint32_t*)(sQh + (rl+8)*FPITCH + cc + 8);
            ql[ks][0] = *(const uint32_t*)(sQl + rl*FPITCH + cc);
            ql[ks][1] = *(const uint32_t*)(sQl + (rl+8)*FPITCH + cc);
            ql[ks][2] = *(const uint32_t*)(sQl + rl*FPITCH + cc + 8);
            ql[ks][3] = *(const uint32_t*)(sQl + (rl+8)*FPITCH + cc + 8);
        }
    }

    int row0 = qbase + warp*16 + grp;
    int row1 = row0 + 8;

    float m0 = -1e30f, m1 = -1e30f, l0 = 0.f, l1 = 0.f;
    float o[8][4];
    #pragma unroll
    for (int j = 0; j < 8; j++)
        #pragma unroll
        for (int q = 0; q < 4; q++) o[j][q] = 0.f;

    const float L2E = 1.4426950408889634f;
    const uint32_t ONES2 = 0x3C003C00u;   // {1.0h, 1.0h}

    for (int jt = 0; jt < ntiles; jt++) {
        int s0 = jt * 64;
        int st = jt & 1;
        asm volatile("cp.async.wait_group 0;" ::: "memory");
        __syncthreads();
        if (jt + 1 < ntiles) issue(jt + 1);

        __half* sKh = (__half*)(smraw + FSM_STAGE0 + st*FSM_STAGE_SZ);
        __half* sKl = sKh + FSM_REG/2;
        __half* sVh = sKh + FSM_REG;
        __half* sVl = sKh + 3*FSM_REG/2;
        float* mfs = (float*)(smraw + FSM_MASK + st*256);

        // ---- S = Q K^T (fp16 split, 3 terms) ----
        float s[8][4];
        #pragma unroll
        for (int j = 0; j < 8; j++)
            #pragma unroll
            for (int q = 0; q < 4; q++) s[j][q] = 0.f;

        #pragma unroll
        for (int ks = 0; ks < 4; ks++) {
            int cc = thr4*2 + ks*16;
            #pragma unroll
            for (int j = 0; j < 8; j++) {
                int n = j*8 + grp;
                uint32_t bh0 = *(const uint32_t*)(sKh + n*FPITCH + cc);
                uint32_t bh1 = *(const uint32_t*)(sKh + n*FPITCH + cc + 8);
                uint32_t bl0 = *(const uint32_t*)(sKl + n*FPITCH + cc);
                uint32_t bl1 = *(const uint32_t*)(sKl + n*FPITCH + cc + 8);
                mma_f16(s[j], qh[ks], bh0, bh1);
                mma_f16(s[j], qh[ks], bl0, bl1);
                mma_f16(s[j], ql[ks], bh0, bh1);
            }
        }

        // ---- scale + masks + row max ----
        bool diag = (jt >= 2*qt);
        float nm0 = m0, nm1 = m1;
        #pragma unroll
        for (int j = 0; j < 8; j++) {
            int cb = 8*j + 2*thr4;
            float f0 = mfs[cb], f1 = mfs[cb+1];
            float v00 = fmaf(s[j][0], 0.125f, f0);
            float v01 = fmaf(s[j][1], 0.125f, f1);
            float v10 = fmaf(s[j][2], 0.125f, f0);
            float v11 = fmaf(s[j][3], 0.125f, f1);
            if (diag) {
                int ca = s0 + cb;
                if (ca     > row0) v00 = -1e30f;
                if (ca + 1 > row0) v01 = -1e30f;
                if (ca     > row1) v10 = -1e30f;
                if (ca + 1 > row1) v11 = -1e30f;
            }
            s[j][0] = v00; s[j][1] = v01; s[j][2] = v10; s[j][3] = v11;
            nm0 = fmaxf(nm0, fmaxf(v00, v01));
            nm1 = fmaxf(nm1, fmaxf(v10, v11));
        }
        nm0 = fmaxf(nm0, __shfl_xor_sync(0xffffffffu, nm0, 1));
        nm0 = fmaxf(nm0, __shfl_xor_sync(0xffffffffu, nm0, 2));
        nm1 = fmaxf(nm1, __shfl_xor_sync(0xffffffffu, nm1, 1));
        nm1 = fmaxf(nm1, __shfl_xor_sync(0xffffffffu, nm1, 2));

        float c0 = __expf(m0 - nm0), c1 = __expf(m1 - nm1);
        m0 = nm0; m1 = nm1;
        float mb0 = m0 * L2E, mb1 = m1 * L2E;

        // ---- P = exp(s - m): fp16x2 ex2, output directly packed ----
        uint32_t pr[8], ps[8];   // pr: row r pairs, ps: row r+8 pairs
        #pragma unroll
        for (int j = 0; j < 8; j++) {
            float t00 = fmaf(s[j][0], L2E, -mb0);
            float t01 = fmaf(s[j][1], L2E, -mb0);
            float t10 = fmaf(s[j][2], L2E, -mb1);
            float t11 = fmaf(s[j][3], L2E, -mb1);
            uint32_t ta, tb;
            asm("cvt.rn.f16x2.f32 %0, %1, %2;" : "=r"(ta) : "f"(t01), "f"(t00));
            asm("cvt.rn.f16x2.f32 %0, %1, %2;" : "=r"(tb) : "f"(t11), "f"(t10));
            asm("ex2.approx.f16x2 %0, %1;" : "=r"(pr[j]) : "r"(ta));
            asm("ex2.approx.f16x2 %0, %1;" : "=r"(ps[j]) : "r"(tb));
        }

        // ---- l sums via ones-mma (exact fp32 accumulation) ----
        float lacc[4] = {0.f, 0.f, 0.f, 0.f};
        #pragma unroll
        for (int ks = 0; ks < 4; ks++) {
            uint32_t a[4] = {pr[2*ks], ps[2*ks], pr[2*ks+1], ps[2*ks+1]};
            mma_f16(lacc, a, ONES2, ONES2);
        }
        l0 = l0*c0 + lacc[0];
        l1 = l1*c1 + lacc[2];

        #pragma unroll
        for (int j = 0; j < 8; j++) {
            o[j][0] *= c0; o[j][1] *= c0;
            o[j][2] *= c1; o[j][3] *= c1;
        }

        // ---- O += P V (2 terms: P fp16-accurate) ----
        #pragma unroll
        for (int ks = 0; ks < 4; ks++) {
            uint32_t a[4] = {pr[2*ks], ps[2*ks], pr[2*ks+1], ps[2*ks+1]};
            int cc = thr4*2 + ks*16;
            #pragma unroll
            for (int j = 0; j < 8; j++) {
                int n = j*8 + grp;
                uint32_t vh0 = *(const uint32_t*)(sVh + n*FPITCH + cc);
                uint32_t vh1 = *(const uint32_t*)(sVh + n*FPITCH + cc + 8);
                uint32_t vl0 = *(const uint32_t*)(sVl + n*FPITCH + cc);
                uint32_t vl1 = *(const uint32_t*)(sVl + n*FPITCH + cc + 8);
                mma_f16(o[j], a, vh0, vh1);
                mma_f16(o[j], a, vl0, vl1);
            }
        }
    }

    // ---- epilogue: [B,T,E], pre-rounded to tf32 for gemm_out ----
    float inv0 = 1.f / l0, inv1 = 1.f / l1;
    float* O0 = g_ao + ((size_t)(b*SEQ) + row0)*EMBED + h*HDIM;
    float* O1 = g_ao + ((size_t)(b*SEQ) + row1)*EMBED + h*HDIM;
    #pragma unroll
    for (int j = 0; j < 8; j++) {
        int col = 8*j + 2*thr4;
        uint2 r0 = make_uint2(f2tf32(o[j][0]*inv0), f2tf32(o[j][1]*inv0));
        uint2 r1 = make_uint2(f2tf32(o[j][2]*inv1), f2tf32(o[j][3]*inv1));
        *reinterpret_cast<uint2*>(O0 + col) = r0;
        *reinterpret_cast<uint2*>(O1 + col) = r1;
    }
}

// ---------------------------------------------------------------------------
extern "C" void kernel_launch(void* const* d_in, const int* in_sizes, int n_in,
                              void* d_out, int out_size)
{
    const float* query = (const float*)d_in[0];
    const float* key   = (const float*)d_in[1];
    const float* value = (const float*)d_in[2];
    const unsigned char* kpm = (const unsigned char*)d_in[3];
    const float* Wq = (const float*)d_in[4];
    const float* bq = (const float*)d_in[5];
    const float* Wk = (const float*)d_in[6];
    const float* bk = (const float*)d_in[7];
    const float* Wv = (const float*)d_in[8];
    const float* bv = (const float*)d_in[9];
    const float* Wo = (const float*)d_in[10];
    const float* bo = (const float*)d_in[11];
    float* out = (float*)d_out;

    prepass<<<16384, 256>>>(query, key, value, Wq, Wk, Wv, Wo);
    mask_prep<<<16, 256>>>(kpm);

    cudaFuncSetAttribute(gemm_qkv, cudaFuncAttributeMaxDynamicSharedMemorySize, GEMM_SMEM);
    cudaFuncSetAttribute(gemm_out, cudaFuncAttributeMaxDynamicSharedMemorySize, GEMM_SMEM);

    dim3 gqkv(EMBED/128, MROWS/128, 3);   // (8, 32, 3)
    gemm_qkv<<<gqkv, 256, GEMM_SMEM>>>(bq, bk, bv);

    cudaFuncSetAttribute(flash_attn_mma, cudaFuncAttributeMaxDynamicSharedMemorySize, FLASH_SMEM);
    flash_attn_mma<<<dim3(SEQ/128, NHEAD, BATCH), 256, FLASH_SMEM>>>();

    dim3 gout(EMBED/128, MROWS/128);
    gemm_out<<<gout, 256, GEMM_SMEM>>>(bo, out);
}

// round 15
// speedup vs baseline: 1.2285x; 1.0183x over previous
#include <cuda_runtime.h>
#include <cuda_fp16.h>
#include <cstdint>

#define EMBED 1024
#define NHEAD 16
#define HDIM  64
#define BATCH 2
#define SEQ   2048
#define MROWS (BATCH*SEQ)   // 4096

// tf32-rounded copies of inputs / weights
__device__ float g_qc[MROWS*EMBED];
__device__ float g_kc[MROWS*EMBED];
__device__ float g_vc[MROWS*EMBED];
__device__ float g_w4[4*EMBED*EMBED];         // Wq | Wk | Wv | Wo
// fp16 hi/lo projections: Q,K in [B,H,T,D]; V in [B,H,D,T] (transposed)
__device__ __half g_qh[BATCH*NHEAD*SEQ*HDIM];
__device__ __half g_ql[BATCH*NHEAD*SEQ*HDIM];
__device__ __half g_kh[BATCH*NHEAD*SEQ*HDIM];
__device__ __half g_kl[BATCH*NHEAD*SEQ*HDIM];
__device__ __half g_vh[BATCH*NHEAD*SEQ*HDIM];
__device__ __half g_vl[BATCH*NHEAD*SEQ*HDIM];
__device__ float g_maskf[BATCH*SEQ];          // 0 or -1e30
__device__ float g_ao[MROWS*EMBED];           // attention out, [B,T,E] (tf32-rounded)

__device__ __forceinline__ uint32_t f2tf32(float x) {
    uint32_t r;
    asm("cvt.rna.tf32.f32 %0, %1;" : "=r"(r) : "f"(x));
    return r;
}

__device__ __forceinline__ uint32_t smem_u32(const void* p) {
    uint32_t a;
    asm("{ .reg .u64 t; cvta.to.shared.u64 t, %1; cvt.u32.u64 %0, t; }" : "=r"(a) : "l"(p));
    return a;
}

// ---------------------------------------------------------------------------
// Prepass: tf32-round inputs + weights; float mask.
// ---------------------------------------------------------------------------
__global__ __launch_bounds__(256) void prepass(
    const float* __restrict__ q, const float* __restrict__ k, const float* __restrict__ v,
    const float* __restrict__ Wq, const float* __restrict__ Wk,
    const float* __restrict__ Wv, const float* __restrict__ Wo)
{
    int idx = blockIdx.x * 256 + threadIdx.x;       // float4 index
    const float* src; float* dst; int off;
    if (idx < 3145728) {
        int seg = idx >> 20;
        off = idx & 1048575;
        src = (seg == 0) ? q : (seg == 1) ? k : v;
        dst = (seg == 0) ? g_qc : (seg == 1) ? g_kc : g_vc;
    } else {
        int r = idx - 3145728;
        int seg = r >> 18;
        off = r & 262143;
        src = (seg == 0) ? Wq : (seg == 1) ? Wk : (seg == 2) ? Wv : Wo;
        dst = g_w4 + (size_t)seg * EMBED * EMBED;
    }
    float4 x = reinterpret_cast<const float4*>(src)[off];
    uint4 t = make_uint4(f2tf32(x.x), f2tf32(x.y), f2tf32(x.z), f2tf32(x.w));
    reinterpret_cast<uint4*>(dst)[off] = t;
}

__global__ __launch_bounds__(256) void mask_prep(const unsigned char* __restrict__ kpm)
{
    int i = blockIdx.x * 256 + threadIdx.x;
    if (i < BATCH*SEQ) g_maskf[i] = kpm[i] ? -1e30f : 0.0f;
}

// ---------------------------------------------------------------------------
// TF32 GEMM v2: 128 threads, 4 warps of 64x64 warp-tiles (crossbar traffic
// 96->64 KB per chunk), 2-stage cp.async, BK=32, pitch 36, 2 CTAs/SM.
// mode: 0 = fp32 [M,E]; 1 = fp16 hi/lo [B,H,T,D]; 2 = fp16 hi/lo [B,H,D,T].
// ---------------------------------------------------------------------------
__device__ __forceinline__ void mma_tf32(float* c, const uint32_t* a,
                                         uint32_t b0, uint32_t b1) {
    asm volatile(
        "mma.sync.aligned.m16n8k8.row.col.f32.tf32.tf32.f32 "
        "{%0,%1,%2,%3}, {%4,%5,%6,%7}, {%8,%9}, {%0,%1,%2,%3};"
        : "+f"(c[0]), "+f"(c[1]), "+f"(c[2]), "+f"(c[3])
        : "r"(a[0]), "r"(a[1]), "r"(a[2]), "r"(a[3]), "r"(b0), "r"(b1));
}

#define GP 36
#define GA_WORDS (128*GP)
#define GSTAGE   (2*GA_WORDS)
#define GEMM_SMEM (2*GSTAGE*4)   // 73728

__device__ __forceinline__ void gemm_body(
    const float* __restrict__ A, const float* __restrict__ W,
    const float* __restrict__ bias, float* __restrict__ Cf,
    __half* __restrict__ Ch, __half* __restrict__ Cl,
    int m0, int n0, int mode)
{
    const int K = EMBED;
    extern __shared__ uint32_t gsm[];
    uint32_t sbase = smem_u32(gsm);

    int tid  = threadIdx.x;
    int lane = tid & 31;
    int warp = tid >> 5;                 // 0..3
    int m0w = (warp >> 1) * 64;
    int n0w = (warp & 1) * 64;

    float c[4][8][4];
    #pragma unroll
    for (int mi = 0; mi < 4; mi++)
        #pragma unroll
        for (int ni = 0; ni < 8; ni++)
            #pragma unroll
            for (int q = 0; q < 4; q++) c[mi][ni][q] = 0.f;

    auto issue = [&](int k0, int s) {
        #pragma unroll
        for (int i = 0; i < 8; i++) {
            int idx = tid + i*128;
            int r = idx >> 3, c4 = (idx & 7) << 2;
            uint32_t da = sbase + (uint32_t)(s*GSTAGE + r*GP + c4) * 4u;
            const float* ga = A + (size_t)(m0 + r) * K + k0 + c4;
            asm volatile("cp.async.cg.shared.global [%0], [%1], 16;" :: "r"(da), "l"(ga));
            uint32_t dw = da + GA_WORDS * 4u;
            const float* gw = W + (size_t)(n0 + r) * K + k0 + c4;
            asm volatile("cp.async.cg.shared.global [%0], [%1], 16;" :: "r"(dw), "l"(gw));
        }
        asm volatile("cp.async.commit_group;" ::: "memory");
    };

    issue(0, 0);

    const int NCHUNK = K / 32;   // 32
    for (int ch = 0; ch < NCHUNK; ch++) {
        asm volatile("cp.async.wait_group 0;" ::: "memory");
        __syncthreads();
        if (ch + 1 < NCHUNK) issue((ch + 1) * 32, (ch + 1) & 1);

        const uint32_t* As = gsm + (ch & 1) * GSTAGE;
        const uint32_t* Ws = As + GA_WORDS;
        #pragma unroll
        for (int kk = 0; kk < 32; kk += 8) {
            int kb = kk + (lane & 3);
            uint32_t a[4][4];
            #pragma unroll
            for (int mi = 0; mi < 4; mi++) {
                int r = m0w + mi * 16 + (lane >> 2);
                a[mi][0] = As[r*GP + kb];
                a[mi][1] = As[(r + 8)*GP + kb];
                a[mi][2] = As[r*GP + kb + 4];
                a[mi][3] = As[(r + 8)*GP + kb + 4];
            }
            #pragma unroll
            for (int ni = 0; ni < 8; ni++) {
                int rn = n0w + ni * 8 + (lane >> 2);
                uint32_t b0 = Ws[rn*GP + kb];
                uint32_t b1 = Ws[rn*GP + kb + 4];
                #pragma unroll
                for (int mi = 0; mi < 4; mi++)
                    mma_tf32(c[mi][ni], a[mi], b0, b1);
            }
        }
        __syncthreads();
    }

    #pragma unroll
    for (int mi = 0; mi < 4; mi++) {
        int rbase = m0 + m0w + mi * 16 + (lane >> 2);
        #pragma unroll
        for (int ni = 0; ni < 8; ni++) {
            int col = n0 + n0w + ni * 8 + 2 * (lane & 3);    // even
            float bv0 = bias[col], bv1 = bias[col + 1];
            #pragma unroll
            for (int half = 0; half < 2; half++) {
                int m = rbase + half * 8;
                float v0 = c[mi][ni][half * 2 + 0] + bv0;
                float v1 = c[mi][ni][half * 2 + 1] + bv1;
                if (mode == 0) {
                    Cf[(size_t)m * EMBED + col]     = v0;
                    Cf[(size_t)m * EMBED + col + 1] = v1;
                } else {
                    int bb = m >> 11, t = m & 2047;
                    int hh = col >> 6, d = col & 63;
                    __half h0 = __float2half(v0), h1 = __float2half(v1);
                    __half l0v = __float2half(v0 - __half2float(h0));
                    __half l1v = __float2half(v1 - __half2float(h1));
                    if (mode == 1) {
                        size_t base = (((size_t)(bb * NHEAD + hh)) * SEQ + t) * HDIM + d;
                        __half2 hp = __halves2half2(h0, h1);
                        __half2 lp = __halves2half2(l0v, l1v);
                        reinterpret_cast<uint32_t*>(Ch)[base >> 1] = *reinterpret_cast<uint32_t*>(&hp);
                        reinterpret_cast<uint32_t*>(Cl)[base >> 1] = *reinterpret_cast<uint32_t*>(&lp);
                    } else {   // mode 2: transposed [B,H,D,T]
                        size_t o0 = (((size_t)(bb * NHEAD + hh)) * HDIM + d) * SEQ + t;
                        Ch[o0]       = h0;
                        Ch[o0 + SEQ] = h1;
                        Cl[o0]       = l0v;
                        Cl[o0 + SEQ] = l1v;
                    }
                }
            }
        }
    }
}

__global__ __launch_bounds__(128) void gemm_qkv(
    const float* __restrict__ bq, const float* __restrict__ bk, const float* __restrict__ bv)
{
    int z = blockIdx.z;
    const float* A = (z == 0) ? g_qc : (z == 1) ? g_kc : g_vc;
    const float* W = g_w4 + (size_t)z * EMBED * EMBED;
    const float* B = (z == 0) ? bq : (z == 1) ? bk : bv;
    __half* Ch = (z == 0) ? g_qh : (z == 1) ? g_kh : g_vh;
    __half* Cl = (z == 0) ? g_ql : (z == 1) ? g_kl : g_vl;
    gemm_body(A, W, B, nullptr, Ch, Cl, blockIdx.y * 128, blockIdx.x * 128,
              (z == 2) ? 2 : 1);
}

__global__ __launch_bounds__(128) void gemm_out(
    const float* __restrict__ bias, float* __restrict__ C)
{
    gemm_body(g_ao, g_w4 + (size_t)3 * EMBED * EMBED, bias, C,
              nullptr, nullptr, blockIdx.y * 128, blockIdx.x * 128, 0);
}

// ---------------------------------------------------------------------------
// Flash attention (unchanged from R14): fp16 split mma; ex2.approx.f16x2;
// l via ones-mma; 2-stage cp.async staging (V pre-transposed).
// ---------------------------------------------------------------------------
__device__ __forceinline__ void mma_f16(float* c, const uint32_t* a,
                                        uint32_t b0, uint32_t b1) {
    asm volatile(
        "mma.sync.aligned.m16n8k16.row.col.f32.f16.f16.f32 "
        "{%0,%1,%2,%3}, {%4,%5,%6,%7}, {%8,%9}, {%0,%1,%2,%3};"
        : "+f"(c[0]), "+f"(c[1]), "+f"(c[2]), "+f"(c[3])
        : "r"(a[0]), "r"(a[1]), "r"(a[2]), "r"(a[3]), "r"(b0), "r"(b1));
}

#define FPITCH 72
#define FSM_STAGE0   36864
#define FSM_STAGE_SZ 36864
#define FSM_REG      9216
#define FSM_MASK     (FSM_STAGE0 + 2*FSM_STAGE_SZ)   // 110592
#define FLASH_SMEM   (FSM_MASK + 2*256)              // 111104

__global__ __launch_bounds__(256, 1) void flash_attn_mma()
{
    extern __shared__ __align__(16) char smraw[];
    __half* sQh = (__half*)smraw;
    __half* sQl = sQh + 128*FPITCH;
    uint32_t sb = smem_u32(smraw);

    int tid  = threadIdx.x;
    int lane = tid & 31, warp = tid >> 5;
    int grp  = lane >> 2, thr4 = lane & 3;
    int qt = (int)gridDim.x - 1 - (int)blockIdx.x;   // heavy tiles first
    int h = blockIdx.y, b = blockIdx.z;
    int qbase = qt * 128;

    size_t headoff = ((size_t)(b*NHEAD + h))*SEQ*HDIM;
    const uint32_t* Qh32 = (const uint32_t*)g_qh + (headoff + (size_t)qbase*HDIM)/2;
    const uint32_t* Ql32 = (const uint32_t*)g_ql + (headoff + (size_t)qbase*HDIM)/2;
    const char* khg = (const char*)g_kh + headoff*2;
    const char* klg = (const char*)g_kl + headoff*2;
    const char* vhg = (const char*)g_vh + headoff*2;   // [D][T] layout
    const char* vlg = (const char*)g_vl + headoff*2;
    const char* mfg = (const char*)(g_maskf + (size_t)b*SEQ);

    const int ntiles = 2*qt + 2;

    auto issue = [&](int jt) {
        int st = jt & 1;
        int s0 = jt * 64;
        uint32_t base = sb + FSM_STAGE0 + st*FSM_STAGE_SZ;
        #pragma unroll
        for (int i = 0; i < 2; i++) {
            int c = tid + i*256;            // 0..511
            int row = c >> 3;
            int o16 = (c & 7) * 16;
            uint32_t doff = (uint32_t)(row*144 + o16);
            const char* ksrc = khg + (size_t)(s0 + row)*128 + o16;
            asm volatile("cp.async.cg.shared.global [%0], [%1], 16;" :: "r"(base + doff), "l"(ksrc));
            const char* ksrc2 = klg + (size_t)(s0 + row)*128 + o16;
            asm volatile("cp.async.cg.shared.global [%0], [%1], 16;" :: "r"(base + FSM_REG + doff), "l"(ksrc2));
            const char* vsrc = vhg + (size_t)row*(SEQ*2) + s0*2 + o16;
            asm volatile("cp.async.cg.shared.global [%0], [%1], 16;" :: "r"(base + 2*FSM_REG + doff), "l"(vsrc));
            const char* vsrc2 = vlg + (size_t)row*(SEQ*2) + s0*2 + o16;
            asm volatile("cp.async.cg.shared.global [%0], [%1], 16;" :: "r"(base + 3*FSM_REG + doff), "l"(vsrc2));
        }
        if (tid < 16) {
            uint32_t dm = sb + FSM_MASK + st*256 + tid*16;
            const char* ms = mfg + (size_t)s0*4 + tid*16;
            asm volatile("cp.async.cg.shared.global [%0], [%1], 16;" :: "r"(dm), "l"(ms));
        }
        asm volatile("cp.async.commit_group;" ::: "memory");
    };

    issue(0);

    // ---- stage Q (pure copy, once) ----
    #pragma unroll
    for (int i = 0; i < 8; i++) {
        int e = tid + i*256;
        int r = e >> 4, c4 = (e & 15) << 2;
        int gi = (r*HDIM + c4) >> 1;
        *reinterpret_cast<uint2*>(sQh + r*FPITCH + c4) = *reinterpret_cast<const uint2*>(Qh32 + gi);
        *reinterpret_cast<uint2*>(sQl + r*FPITCH + c4) = *reinterpret_cast<const uint2*>(Ql32 + gi);
    }
    __syncthreads();

    // ---- preload Q fragments ----
    uint32_t qh[4][4], ql[4][4];
    {
        int rl = warp*16 + grp;
        #pragma unroll
        for (int ks = 0; ks < 4; ks++) {
            int cc = thr4*2 + ks*16;
            qh[ks][0] = *(const uint32_t*)(sQh + rl*FPITCH + cc);
            qh[ks][1] = *(const uint32_t*)(sQh + (rl+8)*FPITCH + cc);
            qh[ks][2] = *(const uint32_t*)(sQh + rl*FPITCH + cc + 8);
            qh[ks][3] = *(const uint32_t*)(sQh + (rl+8)*FPITCH + cc + 8);
            ql[ks][0] = *(const uint32_t*)(sQl + rl*FPITCH + cc);
            ql[ks][1] = *(const uint32_t*)(sQl + (rl+8)*FPITCH + cc);
            ql[ks][2] = *(const uint32_t*)(sQl + rl*FPITCH + cc + 8);
            ql[ks][3] = *(const uint32_t*)(sQl + (rl+8)*FPITCH + cc + 8);
        }
    }

    int row0 = qbase + warp*16 + grp;
    int row1 = row0 + 8;

    float m0 = -1e30f, m1 = -1e30f, l0 = 0.f, l1 = 0.f;
    float o[8][4];
    #pragma unroll
    for (int j = 0; j < 8; j++)
        #pragma unroll
        for (int q = 0; q < 4; q++) o[j][q] = 0.f;

    const float L2E = 1.4426950408889634f;
    const uint32_t ONES2 = 0x3C003C00u;   // {1.0h, 1.0h}

    for (int jt = 0; jt < ntiles; jt++) {
        int s0 = jt * 64;
        int st = jt & 1;
        asm volatile("cp.async.wait_group 0;" ::: "memory");
        __syncthreads();
        if (jt + 1 < ntiles) issue(jt + 1);

        __half* sKh = (__half*)(smraw + FSM_STAGE0 + st*FSM_STAGE_SZ);
        __half* sKl = sKh + FSM_REG/2;
        __half* sVh = sKh + FSM_REG;
        __half* sVl = sKh + 3*FSM_REG/2;
        float* mfs = (float*)(smraw + FSM_MASK + st*256);

        // ---- S = Q K^T (fp16 split, 3 terms) ----
        float s[8][4];
        #pragma unroll
        for (int j = 0; j < 8; j++)
            #pragma unroll
            for (int q = 0; q < 4; q++) s[j][q] = 0.f;

        #pragma unroll
        for (int ks = 0; ks < 4; ks++) {
            int cc = thr4*2 + ks*16;
            #pragma unroll
            for (int j = 0; j < 8; j++) {
                int n = j*8 + grp;
                uint32_t bh0 = *(const uint32_t*)(sKh + n*FPITCH + cc);
                uint32_t bh1 = *(const uint32_t*)(sKh + n*FPITCH + cc + 8);
                uint32_t bl0 = *(const uint32_t*)(sKl + n*FPITCH + cc);
                uint32_t bl1 = *(const uint32_t*)(sKl + n*FPITCH + cc + 8);
                mma_f16(s[j], qh[ks], bh0, bh1);
                mma_f16(s[j], qh[ks], bl0, bl1);
                mma_f16(s[j], ql[ks], bh0, bh1);
            }
        }

        // ---- scale + masks + row max ----
        bool diag = (jt >= 2*qt);
        float nm0 = m0, nm1 = m1;
        #pragma unroll
        for (int j = 0; j < 8; j++) {
            int cb = 8*j + 2*thr4;
            float f0 = mfs[cb], f1 = mfs[cb+1];
            float v00 = fmaf(s[j][0], 0.125f, f0);
            float v01 = fmaf(s[j][1], 0.125f, f1);
            float v10 = fmaf(s[j][2], 0.125f, f0);
            float v11 = fmaf(s[j][3], 0.125f, f1);
            if (diag) {
                int ca = s0 + cb;
                if (ca     > row0) v00 = -1e30f;
                if (ca + 1 > row0) v01 = -1e30f;
                if (ca     > row1) v10 = -1e30f;
                if (ca + 1 > row1) v11 = -1e30f;
            }
            s[j][0] = v00; s[j][1] = v01; s[j][2] = v10; s[j][3] = v11;
            nm0 = fmaxf(nm0, fmaxf(v00, v01));
            nm1 = fmaxf(nm1, fmaxf(v10, v11));
        }
        nm0 = fmaxf(nm0, __shfl_xor_sync(0xffffffffu, nm0, 1));
        nm0 = fmaxf(nm0, __shfl_xor_sync(0xffffffffu, nm0, 2));
        nm1 = fmaxf(nm1, __shfl_xor_sync(0xffffffffu, nm1, 1));
        nm1 = fmaxf(nm1, __shfl_xor_sync(0xffffffffu, nm1, 2));

        float c0 = __expf(m0 - nm0), c1 = __expf(m1 - nm1);
        m0 = nm0; m1 = nm1;
        float mb0 = m0 * L2E, mb1 = m1 * L2E;

        // ---- P = exp(s - m): fp16x2 ex2, output directly packed ----
        uint32_t pr[8], ps[8];
        #pragma unroll
        for (int j = 0; j < 8; j++) {
            float t00 = fmaf(s[j][0], L2E, -mb0);
            float t01 = fmaf(s[j][1], L2E, -mb0);
            float t10 = fmaf(s[j][2], L2E, -mb1);
            float t11 = fmaf(s[j][3], L2E, -mb1);
            uint32_t ta, tb;
            asm("cvt.rn.f16x2.f32 %0, %1, %2;" : "=r"(ta) : "f"(t01), "f"(t00));
            asm("cvt.rn.f16x2.f32 %0, %1, %2;" : "=r"(tb) : "f"(t11), "f"(t10));
            asm("ex2.approx.f16x2 %0, %1;" : "=r"(pr[j]) : "r"(ta));
            asm("ex2.approx.f16x2 %0, %1;" : "=r"(ps[j]) : "r"(tb));
        }

        // ---- l sums via ones-mma ----
        float lacc[4] = {0.f, 0.f, 0.f, 0.f};
        #pragma unroll
        for (int ks = 0; ks < 4; ks++) {
            uint32_t a[4] = {pr[2*ks], ps[2*ks], pr[2*ks+1], ps[2*ks+1]};
            mma_f16(lacc, a, ONES2, ONES2);
        }
        l0 = l0*c0 + lacc[0];
        l1 = l1*c1 + lacc[2];

        #pragma unroll
        for (int j = 0; j < 8; j++) {
            o[j][0] *= c0; o[j][1] *= c0;
            o[j][2] *= c1; o[j][3] *= c1;
        }

        // ---- O += P V (2 terms) ----
        #pragma unroll
        for (int ks = 0; ks < 4; ks++) {
            uint32_t a[4] = {pr[2*ks], ps[2*ks], pr[2*ks+1], ps[2*ks+1]};
            int cc = thr4*2 + ks*16;
            #pragma unroll
            for (int j = 0; j < 8; j++) {
                int n = j*8 + grp;
                uint32_t vh0 = *(const uint32_t*)(sVh + n*FPITCH + cc);
                uint32_t vh1 = *(const uint32_t*)(sVh + n*FPITCH + cc + 8);
                uint32_t vl0 = *(const uint32_t*)(sVl + n*FPITCH + cc);
                uint32_t vl1 = *(const uint32_t*)(sVl + n*FPITCH + cc + 8);
                mma_f16(o[j], a, vh0, vh1);
                mma_f16(o[j], a, vl0, vl1);
            }
        }
    }

    // ---- epilogue: [B,T,E], pre-rounded to tf32 for gemm_out ----
    float inv0 = 1.f / l0, inv1 = 1.f / l1;
    float* O0 = g_ao + ((size_t)(b*SEQ) + row0)*EMBED + h*HDIM;
    float* O1 = g_ao + ((size_t)(b*SEQ) + row1)*EMBED + h*HDIM;
    #pragma unroll
    for (int j = 0; j < 8; j++) {
        int col = 8*j + 2*thr4;
        uint2 r0 = make_uint2(f2tf32(o[j][0]*inv0), f2tf32(o[j][1]*inv0));
        uint2 r1 = make_uint2(f2tf32(o[j][2]*inv1), f2tf32(o[j][3]*inv1));
        *reinterpret_cast<uint2*>(O0 + col) = r0;
        *reinterpret_cast<uint2*>(O1 + col) = r1;
    }
}

// ---------------------------------------------------------------------------
extern "C" void kernel_launch(void* const* d_in, const int* in_sizes, int n_in,
                              void* d_out, int out_size)
{
    const float* query = (const float*)d_in[0];
    const float* key   = (const float*)d_in[1];
    const float* value = (const float*)d_in[2];
    const unsigned char* kpm = (const unsigned char*)d_in[3];
    const float* Wq = (const float*)d_in[4];
    const float* bq = (const float*)d_in[5];
    const float* Wk = (const float*)d_in[6];
    const float* bk = (const float*)d_in[7];
    const float* Wv = (const float*)d_in[8];
    const float* bv = (const float*)d_in[9];
    const float* Wo = (const float*)d_in[10];
    const float* bo = (const float*)d_in[11];
    float* out = (float*)d_out;

    prepass<<<16384, 256>>>(query, key, value, Wq, Wk, Wv, Wo);
    mask_prep<<<16, 256>>>(kpm);

    cudaFuncSetAttribute(gemm_qkv, cudaFuncAttributeMaxDynamicSharedMemorySize, GEMM_SMEM);
    cudaFuncSetAttribute(gemm_out, cudaFuncAttributeMaxDynamicSharedMemorySize, GEMM_SMEM);

    dim3 gqkv(EMBED/128, MROWS/128, 3);   // (8, 32, 3)
    gemm_qkv<<<gqkv, 128, GEMM_SMEM>>>(bq, bk, bv);

    cudaFuncSetAttribute(flash_attn_mma, cudaFuncAttributeMaxDynamicSharedMemorySize, FLASH_SMEM);
    flash_attn_mma<<<dim3(SEQ/128, NHEAD, BATCH), 256, FLASH_SMEM>>>();

    dim3 gout(EMBED/128, MROWS/128);
    gemm_out<<<gout, 128, GEMM_SMEM>>>(bo, out);
}